// round 12
// baseline (speedup 1.0000x reference)
#include <cuda_runtime.h>
#include <cuda_fp16.h>
#include <cstdint>
#include <cstddef>

#define NPTS 500000
#define DIM  128
#define KC   1024

// ---------------- scratch ----------------
__device__ float g_sums[KC * DIM];
__device__ float g_counts[KC];
__device__ float g_c2[KC];
__device__ __half g_cent_hi[KC * DIM];   // fp16 splits of -2*centroid
__device__ __half g_cent_mi[KC * DIM];

// ---------------- helpers ----------------
__device__ __forceinline__ uint32_t smem_u32(const void* p) {
    uint32_t a;
    asm("{ .reg .u64 t; cvta.to.shared.u64 t, %1; cvt.u32.u64 %0, t; }" : "=r"(a) : "l"(p));
    return a;
}
__device__ __forceinline__ void ldsm_x4(uint32_t* r, uint32_t addr) {
    asm volatile("ldmatrix.sync.aligned.m8n8.x4.shared.b16 {%0,%1,%2,%3}, [%4];"
        : "=r"(r[0]), "=r"(r[1]), "=r"(r[2]), "=r"(r[3]) : "r"(addr));
}
__device__ __forceinline__ void mma_f16(float* d, const uint32_t* a, uint32_t b0, uint32_t b1) {
    asm volatile("mma.sync.aligned.m16n8k16.row.col.f32.f16.f16.f32 "
        "{%0,%1,%2,%3}, {%4,%5,%6,%7}, {%8,%9}, {%0,%1,%2,%3};"
        : "+f"(d[0]), "+f"(d[1]), "+f"(d[2]), "+f"(d[3])
        : "r"(a[0]), "r"(a[1]), "r"(a[2]), "r"(a[3]), "r"(b0), "r"(b1));
}
__device__ __forceinline__ void cp16(uint32_t dst, const void* src) {
    asm volatile("cp.async.cg.shared.global [%0], [%1], 16;" :: "r"(dst), "l"(src) : "memory");
}
#define CP_COMMIT() asm volatile("cp.async.commit_group;" ::: "memory")
#define CP_WAIT0()  asm volatile("cp.async.wait_group 0;" ::: "memory")
#define CP_WAIT1()  asm volatile("cp.async.wait_group 1;" ::: "memory")

// ---------------- kernel 1: zero scratch ----------------
__global__ void zero_kernel() {
    int i = blockIdx.x * blockDim.x + threadIdx.x;
    if (i < KC * DIM) g_sums[i] = 0.0f;
    if (i < KC)       g_counts[i] = 0.0f;
}

// ---------------- kernel 2: segment sum ----------------
__global__ void segsum_kernel(const float* __restrict__ vecs,
                              const int*   __restrict__ asg) {
    int gw   = (blockIdx.x * blockDim.x + threadIdx.x) >> 5;
    int lane = threadIdx.x & 31;
    if (gw >= NPTS) return;
    int k = asg[gw];
    float4 v = *((const float4*)(vecs + (size_t)gw * DIM) + lane);
    atomicAdd(((float4*)(g_sums + (size_t)k * DIM)) + lane, v);
    if (lane == 0) atomicAdd(&g_counts[k], 1.0f);
}

// ---------------- kernel 3: centroids, c2, -2c fp16 splits ----------------
__global__ void finalize_kernel(float* __restrict__ out_cent) {
    int k = blockIdx.x;
    int d = threadIdx.x;
    float c = g_sums[k * DIM + d] / g_counts[k];
    out_cent[k * DIM + d] = c;

    float m = -2.0f * c;
    __half h = __float2half_rn(m);
    __half mi = __float2half_rn(m - __half2float(h));
    g_cent_hi[k * DIM + d] = h;
    g_cent_mi[k * DIM + d] = mi;

    float s = c * c;
    #pragma unroll
    for (int o = 16; o > 0; o >>= 1) s += __shfl_down_sync(0xffffffffu, s, o);
    __shared__ float ws[4];
    if ((d & 31) == 0) ws[d >> 5] = s;
    __syncthreads();
    if (d == 0) g_c2[k] = (ws[0] + ws[1]) + (ws[2] + ws[3]);
}

// ---------------- kernel 4: mma.sync fp16-split GEMM + argmin ----------------
// 128 points/CTA x 1024 clusters. 4 warps; warp w owns points 32w..32w+31.
// A: 2 fp16 splits of points, swizzled smem [2][128][256B].
// B: 2 fp16 splits of -2c, 32-cluster chunks, cp.async triple-buffered,
//    issue-after-sync, one __syncthreads per chunk.
// DEFERRED FOLD: chunk ch's argmin fold runs interleaved inside chunk ch+1's
// MMA loop (D ping-pong) so fold FADD/FSETP fills issue gaps between HMMAs
// instead of serializing after the k-loop. Fold order unchanged (ascending).
// 3 product passes (hh, hm, mh) accumulate into fp32 D.
#define PTS_CTA 128
#define THR     128
#define CH_N    32
#define CHW     32
#define A_SPLIT 32768
#define A_OFF   0
#define B_OFF   65536
#define B_BUF   16384
#define B_SPLIT 8192
#define NBUF    3
#define SM_TOTAL (B_OFF + NBUF * B_BUF)     // 114688 = 112KB -> 2 CTAs/SM

__device__ __forceinline__ void issue_b_chunk(uint32_t su, int tid, int ch, int buf) {
    #pragma unroll
    for (int s = 0; s < 2; s++) {
        const __half* g = (s == 0) ? g_cent_hi : g_cent_mi;
        const char* gb = (const char*)(g + (size_t)ch * CHW * DIM);
        #pragma unroll
        for (int it = 0; it < 4; it++) {
            int idx = tid + it * THR;          // 0..511
            int row = idx >> 4, kg = idx & 15;
            uint32_t dst = su + B_OFF + (uint32_t)buf * B_BUF
                         + (uint32_t)s * B_SPLIT + (uint32_t)row * 256u
                         + ((uint32_t)(kg ^ (row & 7)) << 4);
            cp16(dst, gb + (size_t)idx * 16);
        }
    }
    CP_COMMIT();
}

__global__ __launch_bounds__(THR, 2)
void argmin_mma_kernel(const float* __restrict__ vecs, float* __restrict__ out_asg) {
    extern __shared__ __align__(1024) char sm[];
    const uint32_t su = smem_u32(sm);
    const int tid  = threadIdx.x;
    const int lane = tid & 31;
    const int w    = tid >> 5;
    const int base = blockIdx.x * PTS_CTA;

    // ---- issue chunk 0/1 B loads first (overlaps A convert) ----
    issue_b_chunk(su, tid, 0, 0);
    issue_b_chunk(su, tid, 1, 1);

    // ---- A convert: fp32 -> 2x fp16 splits into swizzled smem; x2 ----
    // x2 arithmetic order frozen: two serial 64-dim fmaf chains, then one add.
    float s2tot;
    {
        int p = tid;
        int n = base + p; if (n >= NPTS) n = NPTS - 1;
        const uint32_t rowb = (uint32_t)p * 256u;
        const uint32_t psw  = (uint32_t)(p & 7);
        float s2h[2];
        #pragma unroll
        for (int h = 0; h < 2; h++) {
            const float4* src = (const float4*)(vecs + (size_t)n * DIM) + h * 16;
            float s2 = 0.0f;
            #pragma unroll
            for (int j = 0; j < 16; j++) {
                float4 v = src[j];
                int d0 = h * 64 + j * 4;
                #pragma unroll
                for (int q = 0; q < 2; q++) {
                    float a0 = q ? v.z : v.x;
                    float a1 = q ? v.w : v.y;
                    int   d  = d0 + 2 * q;
                    s2 = fmaf(a0, a0, s2); s2 = fmaf(a1, a1, s2);
                    __half h0 = __float2half_rn(a0);
                    __half m0 = __float2half_rn(a0 - __half2float(h0));
                    __half h1 = __float2half_rn(a1);
                    __half m1 = __float2half_rn(a1 - __half2float(h1));
                    uint32_t off = rowb + ((((uint32_t)(d >> 3)) ^ psw) << 4) + (uint32_t)(d & 7) * 2u;
                    __half2 ph(h0, h1), pm(m0, m1);
                    *(uint32_t*)(sm + A_OFF + 0 * A_SPLIT + off) = *(uint32_t*)&ph;
                    *(uint32_t*)(sm + A_OFF + 1 * A_SPLIT + off) = *(uint32_t*)&pm;
                }
            }
            s2h[h] = s2;
        }
        s2tot = s2h[0] + s2h[1];
    }

    const int p0 = w * 32;
    float x2r[2][2];
    #pragma unroll
    for (int mt = 0; mt < 2; mt++)
        #pragma unroll
        for (int hf = 0; hf < 2; hf++)
            x2r[mt][hf] = __shfl_sync(0xffffffffu, s2tot, mt * 16 + hf * 8 + (lane >> 2));

    float best[2][2] = {{3.402823466e38f, 3.402823466e38f},
                        {3.402823466e38f, 3.402823466e38f}};
    int   bi[2][2]   = {{0, 0}, {0, 0}};

    uint32_t abase[2];
    #pragma unroll
    for (int mt = 0; mt < 2; mt++)
        abase[mt] = su + A_OFF + (uint32_t)(p0 + mt * 16 + (lane & 15)) * 256u;
    const uint32_t arsw0 = (uint32_t)((p0 + (lane & 15)) & 7);
    const int akg  = lane >> 4;
    const int brow_local = ((lane >> 4) << 3) + (lane & 7);
    const int bkg_half   = (lane >> 3) & 1;

    float D0[2][4][4], D1[2][4][4];

    // fold one nt-slice of a finished chunk (identical arithmetic/order
    // to the validated fold; only *when* it executes has changed)
    auto fold_piece = [&](float (&Dp)[2][4][4], int nt, float2 c2v, int fch) {
        int cb = fch * CHW + nt * 8 + 2 * (lane & 3);
        float c20 = c2v.x, c21 = c2v.y;
        #pragma unroll
        for (int mt = 0; mt < 2; mt++) {
            float v;
            v = (c20 + x2r[mt][0]) + Dp[mt][nt][0]; if (v < best[mt][0]) { best[mt][0] = v; bi[mt][0] = cb; }
            v = (c21 + x2r[mt][0]) + Dp[mt][nt][1]; if (v < best[mt][0]) { best[mt][0] = v; bi[mt][0] = cb + 1; }
            v = (c20 + x2r[mt][1]) + Dp[mt][nt][2]; if (v < best[mt][1]) { best[mt][1] = v; bi[mt][1] = cb; }
            v = (c21 + x2r[mt][1]) + Dp[mt][nt][3]; if (v < best[mt][1]) { best[mt][1] = v; bi[mt][1] = cb + 1; }
        }
    };

    // one chunk: MMA-accumulate into Dc; interleave the fold of chunk fch
    // (whose results sit in Dp) at ks = 1,3,5,7.
    auto chunk_body = [&](float (&Dc)[2][4][4], float (&Dp)[2][4][4], int ch, int fch) {
        const int buf = ch % NBUF;
        if (ch + 1 < CH_N) { CP_WAIT1(); } else { CP_WAIT0(); }
        __syncthreads();
        if (ch + 2 < CH_N)
            issue_b_chunk(su, tid, ch + 2, (ch + 2) % NBUF);

        float2 c2p[4];
        if (fch >= 0) {
            #pragma unroll
            for (int nt = 0; nt < 4; nt++)
                c2p[nt] = __ldg((const float2*)(g_c2 + fch * CHW + nt * 8 + 2 * (lane & 3)));
        }

        #pragma unroll
        for (int mt = 0; mt < 2; mt++)
            #pragma unroll
            for (int i = 0; i < 4; i++)
                #pragma unroll
                for (int j = 0; j < 4; j++) Dc[mt][i][j] = 0.0f;

        const uint32_t bbase = su + B_OFF + (uint32_t)buf * B_BUF;

        #pragma unroll
        for (int ks = 0; ks < 8; ks++) {
            uint32_t A_[2][2][4];     // [split][mt]
            {
                uint32_t ag = (uint32_t)(ks * 2 + akg);
                uint32_t asw = ((ag ^ arsw0) << 4);
                #pragma unroll
                for (int mt = 0; mt < 2; mt++) {
                    ldsm_x4(A_[0][mt], abase[mt] + 0 * A_SPLIT + asw);
                    ldsm_x4(A_[1][mt], abase[mt] + 1 * A_SPLIT + asw);
                }
            }
            uint32_t B_[2][2][4];     // [split][pp]
            #pragma unroll
            for (int pp = 0; pp < 2; pp++) {
                int r  = pp * 16 + brow_local;
                int kg = ks * 2 + bkg_half;
                uint32_t bad = bbase + (uint32_t)r * 256u + ((uint32_t)(kg ^ (r & 7)) << 4);
                ldsm_x4(B_[0][pp], bad + 0 * B_SPLIT);
                ldsm_x4(B_[1][pp], bad + 1 * B_SPLIT);
            }
            // passes: (sa,sb) = hh, hm, mh
            const int SA[3] = {0, 0, 1};
            const int SB[3] = {0, 1, 0};
            #pragma unroll
            for (int p3 = 0; p3 < 3; p3++) {
                #pragma unroll
                for (int mt = 0; mt < 2; mt++) {
                    #pragma unroll
                    for (int pp = 0; pp < 2; pp++) {
                        mma_f16(Dc[mt][pp * 2 + 0], A_[SA[p3]][mt], B_[SB[p3]][pp][0], B_[SB[p3]][pp][1]);
                        mma_f16(Dc[mt][pp * 2 + 1], A_[SA[p3]][mt], B_[SB[p3]][pp][2], B_[SB[p3]][pp][3]);
                    }
                }
            }
            if (fch >= 0 && (ks & 1))
                fold_piece(Dp, ks >> 1, c2p[ks >> 1], fch);
        }
    };

    // ---- chunk schedule: ch0 (no fold) | pairs | ch31 | final fold(31) ----
    chunk_body(D0, D1, 0, -1);
    #pragma unroll 1
    for (int ch = 1; ch < CH_N - 1; ch += 2) {
        chunk_body(D1, D0, ch,     ch - 1);
        chunk_body(D0, D1, ch + 1, ch);
    }
    chunk_body(D1, D0, CH_N - 1, CH_N - 2);
    {
        float2 c2l[4];
        #pragma unroll
        for (int nt = 0; nt < 4; nt++)
            c2l[nt] = __ldg((const float2*)(g_c2 + (CH_N - 1) * CHW + nt * 8 + 2 * (lane & 3)));
        #pragma unroll
        for (int nt = 0; nt < 4; nt++)
            fold_piece(D1, nt, c2l[nt], CH_N - 1);
    }

    // ---- reduce across the 4 lanes sharing each point row ----
    #pragma unroll
    for (int off = 1; off < 4; off <<= 1) {
        #pragma unroll
        for (int mt = 0; mt < 2; mt++)
            #pragma unroll
            for (int hf = 0; hf < 2; hf++) {
                float ov = __shfl_xor_sync(0xffffffffu, best[mt][hf], off);
                int   oi = __shfl_xor_sync(0xffffffffu, bi[mt][hf],   off);
                if (ov < best[mt][hf] || (ov == best[mt][hf] && oi < bi[mt][hf])) {
                    best[mt][hf] = ov; bi[mt][hf] = oi;
                }
            }
    }
    if ((lane & 3) == 0) {
        #pragma unroll
        for (int mt = 0; mt < 2; mt++) {
            int rA = p0 + mt * 16 + (lane >> 2);
            if (base + rA < NPTS)     out_asg[base + rA]     = (float)bi[mt][0];
            if (base + rA + 8 < NPTS) out_asg[base + rA + 8] = (float)bi[mt][1];
        }
    }
}

// ---------------- launch ----------------
extern "C" void kernel_launch(void* const* d_in, const int* in_sizes, int n_in,
                              void* d_out, int out_size) {
    const float* vecs = (const float*)d_in[0];
    const int*   asg  = (const int*)d_in[1];
    float* out      = (float*)d_out;
    float* out_cent = out;             // [KC*DIM]
    float* out_asg  = out + KC * DIM;  // [NPTS]

    zero_kernel<<<(KC * DIM + 255) / 256, 256>>>();
    segsum_kernel<<<(NPTS * 32) / 256, 256>>>(vecs, asg);
    finalize_kernel<<<KC, DIM>>>(out_cent);

    cudaFuncSetAttribute(argmin_mma_kernel,
                         cudaFuncAttributeMaxDynamicSharedMemorySize, SM_TOTAL);
    int ablocks = (NPTS + PTS_CTA - 1) / PTS_CTA;
    argmin_mma_kernel<<<ablocks, THR, SM_TOTAL>>>(vecs, out_asg);
}

// round 13
// speedup vs baseline: 1.3703x; 1.3703x over previous
#include <cuda_runtime.h>
#include <cuda_fp16.h>
#include <cstdint>
#include <cstddef>

#define NPTS 500000
#define DIM  128
#define KC   1024

// ---------------- scratch ----------------
__device__ float g_sums[KC * DIM];
__device__ float g_counts[KC];
__device__ float g_c2[KC];
__device__ __half g_cent_hi[KC * DIM];   // fp16 splits of -2*centroid
__device__ __half g_cent_mi[KC * DIM];
__device__ int   g_flagged[NPTS];
__device__ int   g_nflag;
__device__ int   g_maxmh_bits;           // max over clusters of ||mh||  (float bits)
__device__ int   g_maxmm_bits;           // max over clusters of ||m - mh|| (float bits)

// ---------------- helpers ----------------
__device__ __forceinline__ uint32_t smem_u32(const void* p) {
    uint32_t a;
    asm("{ .reg .u64 t; cvta.to.shared.u64 t, %1; cvt.u32.u64 %0, t; }" : "=r"(a) : "l"(p));
    return a;
}
__device__ __forceinline__ void ldsm_x4(uint32_t* r, uint32_t addr) {
    asm volatile("ldmatrix.sync.aligned.m8n8.x4.shared.b16 {%0,%1,%2,%3}, [%4];"
        : "=r"(r[0]), "=r"(r[1]), "=r"(r[2]), "=r"(r[3]) : "r"(addr));
}
__device__ __forceinline__ void mma_f16(float* d, const uint32_t* a, uint32_t b0, uint32_t b1) {
    asm volatile("mma.sync.aligned.m16n8k16.row.col.f32.f16.f16.f32 "
        "{%0,%1,%2,%3}, {%4,%5,%6,%7}, {%8,%9}, {%0,%1,%2,%3};"
        : "+f"(d[0]), "+f"(d[1]), "+f"(d[2]), "+f"(d[3])
        : "r"(a[0]), "r"(a[1]), "r"(a[2]), "r"(a[3]), "r"(b0), "r"(b1));
}
__device__ __forceinline__ void cp16(uint32_t dst, const void* src) {
    asm volatile("cp.async.cg.shared.global [%0], [%1], 16;" :: "r"(dst), "l"(src) : "memory");
}
#define CP_COMMIT() asm volatile("cp.async.commit_group;" ::: "memory")
#define CP_WAIT0()  asm volatile("cp.async.wait_group 0;" ::: "memory")
#define CP_WAIT1()  asm volatile("cp.async.wait_group 1;" ::: "memory")

// ---------------- kernel 1: zero scratch ----------------
__global__ void zero_kernel() {
    int i = blockIdx.x * blockDim.x + threadIdx.x;
    if (i < KC * DIM) g_sums[i] = 0.0f;
    if (i < KC)       g_counts[i] = 0.0f;
    if (i == 0) { g_nflag = 0; g_maxmh_bits = 0; g_maxmm_bits = 0; }
}

// ---------------- kernel 2: segment sum ----------------
__global__ void segsum_kernel(const float* __restrict__ vecs,
                              const int*   __restrict__ asg) {
    int gw   = (blockIdx.x * blockDim.x + threadIdx.x) >> 5;
    int lane = threadIdx.x & 31;
    if (gw >= NPTS) return;
    int k = asg[gw];
    float4 v = *((const float4*)(vecs + (size_t)gw * DIM) + lane);
    atomicAdd(((float4*)(g_sums + (size_t)k * DIM)) + lane, v);
    if (lane == 0) atomicAdd(&g_counts[k], 1.0f);
}

// ---------------- kernel 3: centroids, c2, splits, split norms ----------------
__global__ void finalize_kernel(float* __restrict__ out_cent) {
    int k = blockIdx.x;
    int d = threadIdx.x;
    float c = g_sums[k * DIM + d] / g_counts[k];
    out_cent[k * DIM + d] = c;

    float m = -2.0f * c;
    __half h = __float2half_rn(m);
    float mhf = __half2float(h);
    float mmr = m - mhf;                      // residual beyond hh pass
    __half mi = __float2half_rn(mmr);
    g_cent_hi[k * DIM + d] = h;
    g_cent_mi[k * DIM + d] = mi;

    float s  = c * c;
    float sh = mhf * mhf;
    float sr = mmr * mmr;
    #pragma unroll
    for (int o = 16; o > 0; o >>= 1) {
        s  += __shfl_down_sync(0xffffffffu, s,  o);
        sh += __shfl_down_sync(0xffffffffu, sh, o);
        sr += __shfl_down_sync(0xffffffffu, sr, o);
    }
    __shared__ float ws[4], wh[4], wr[4];
    if ((d & 31) == 0) { ws[d >> 5] = s; wh[d >> 5] = sh; wr[d >> 5] = sr; }
    __syncthreads();
    if (d == 0) {
        g_c2[k] = (ws[0] + ws[1]) + (ws[2] + ws[3]);
        float nh = sqrtf((wh[0] + wh[1]) + (wh[2] + wh[3]));
        float nr = sqrtf((wr[0] + wr[1]) + (wr[2] + wr[3]));
        atomicMax(&g_maxmh_bits, __float_as_int(nh));   // norms >= 0
        atomicMax(&g_maxmm_bits, __float_as_int(nr));
    }
}

// ================= phase 1: hh-only MMA argmin + certification =================
// 128 points/CTA x 1024 clusters. 4 warps; warp w owns points 32w..32w+31.
// A: xh fp16, swizzled smem [128][256B]. B: mh, 32-cluster chunks, NBUF=3,
// issue-after-sync. Tracks best AND runner-up; certifies when gap > thr.
#define PTS_CTA 128
#define THR     128
#define CH_N    32
#define CHW     32
#define P1_A    0
#define P1_B    32768
#define P1_BBUF 8192
#define P1_NBUF 3
#define P1_SM   (P1_B + P1_NBUF * P1_BBUF)    // 57344 -> 4 CTAs/SM

__device__ __forceinline__ void p1_issue_b(uint32_t su, int tid, int ch, int buf) {
    const char* gb = (const char*)(g_cent_hi + (size_t)ch * CHW * DIM);
    #pragma unroll
    for (int it = 0; it < 4; it++) {
        int idx = tid + it * THR;          // 0..511
        int row = idx >> 4, kg = idx & 15;
        uint32_t dst = su + P1_B + (uint32_t)buf * P1_BBUF + (uint32_t)row * 256u
                     + ((uint32_t)(kg ^ (row & 7)) << 4);
        cp16(dst, gb + (size_t)idx * 16);
    }
    CP_COMMIT();
}

__global__ __launch_bounds__(THR, 4)
void phase1_kernel(const float* __restrict__ vecs, float* __restrict__ out_asg) {
    extern __shared__ __align__(1024) char sm[];
    const uint32_t su = smem_u32(sm);
    const int tid  = threadIdx.x;
    const int lane = tid & 31;
    const int w    = tid >> 5;
    const int base = blockIdx.x * PTS_CTA;

    const float maxMh = __int_as_float(g_maxmh_bits);
    const float maxMm = __int_as_float(g_maxmm_bits);

    p1_issue_b(su, tid, 0, 0);
    p1_issue_b(su, tid, 1, 1);

    // A convert: fp32 -> xh fp16 (smem); x2 (frozen order), ||xh||^2, ||xmr||^2
    float s2tot, xh2, xmr2;
    {
        int p = tid;
        int n = base + p; if (n >= NPTS) n = NPTS - 1;
        const uint32_t rowb = (uint32_t)p * 256u;
        const uint32_t psw  = (uint32_t)(p & 7);
        float s2h[2]; xh2 = 0.0f; xmr2 = 0.0f;
        #pragma unroll
        for (int h = 0; h < 2; h++) {
            const float4* src = (const float4*)(vecs + (size_t)n * DIM) + h * 16;
            float s2 = 0.0f;
            #pragma unroll
            for (int j = 0; j < 16; j++) {
                float4 v = src[j];
                int d0 = h * 64 + j * 4;
                #pragma unroll
                for (int q = 0; q < 2; q++) {
                    float a0 = q ? v.z : v.x;
                    float a1 = q ? v.w : v.y;
                    int   d  = d0 + 2 * q;
                    s2 = fmaf(a0, a0, s2); s2 = fmaf(a1, a1, s2);
                    __half h0 = __float2half_rn(a0);
                    __half h1 = __float2half_rn(a1);
                    float f0 = __half2float(h0), f1 = __half2float(h1);
                    float r0 = a0 - f0, r1 = a1 - f1;
                    xh2  = fmaf(f0, f0, xh2);  xh2  = fmaf(f1, f1, xh2);
                    xmr2 = fmaf(r0, r0, xmr2); xmr2 = fmaf(r1, r1, xmr2);
                    uint32_t off = rowb + ((((uint32_t)(d >> 3)) ^ psw) << 4) + (uint32_t)(d & 7) * 2u;
                    __half2 ph(h0, h1);
                    *(uint32_t*)(sm + P1_A + off) = *(uint32_t*)&ph;
                }
            }
            s2h[h] = s2;
        }
        s2tot = s2h[0] + s2h[1];
    }

    const int p0 = w * 32;
    float x2r[2][2], thr[2][2];
    #pragma unroll
    for (int mt = 0; mt < 2; mt++)
        #pragma unroll
        for (int hf = 0; hf < 2; hf++) {
            int sl = mt * 16 + hf * 8 + (lane >> 2);
            x2r[mt][hf]  = __shfl_sync(0xffffffffu, s2tot, sl);
            float a2 = __shfl_sync(0xffffffffu, xmr2, sl);
            float h2 = __shfl_sync(0xffffffffu, xh2,  sl);
            thr[mt][hf] = 3.0f * (sqrtf(a2) * (maxMh + maxMm) + sqrtf(h2) * maxMm) + 2e-4f;
        }

    float b1[2][2] = {{3.402823466e38f, 3.402823466e38f},
                      {3.402823466e38f, 3.402823466e38f}};
    float b2[2][2] = {{3.402823466e38f, 3.402823466e38f},
                      {3.402823466e38f, 3.402823466e38f}};
    int   i1[2][2] = {{0, 0}, {0, 0}};

    uint32_t abase[2];
    #pragma unroll
    for (int mt = 0; mt < 2; mt++)
        abase[mt] = su + P1_A + (uint32_t)(p0 + mt * 16 + (lane & 15)) * 256u;
    const uint32_t arsw0 = (uint32_t)((p0 + (lane & 15)) & 7);
    const int akg  = lane >> 4;
    const int brow_local = ((lane >> 4) << 3) + (lane & 7);
    const int bkg_half   = (lane >> 3) & 1;

    for (int ch = 0; ch < CH_N; ch++) {
        const int buf = ch % P1_NBUF;
        if (ch + 1 < CH_N) { CP_WAIT1(); } else { CP_WAIT0(); }
        __syncthreads();
        if (ch + 2 < CH_N) p1_issue_b(su, tid, ch + 2, (ch + 2) % P1_NBUF);

        float2 c2p[4];
        #pragma unroll
        for (int nt = 0; nt < 4; nt++)
            c2p[nt] = __ldg((const float2*)(g_c2 + ch * CHW + nt * 8 + 2 * (lane & 3)));

        float D[2][4][4];
        #pragma unroll
        for (int mt = 0; mt < 2; mt++)
            #pragma unroll
            for (int i = 0; i < 4; i++)
                #pragma unroll
                for (int j = 0; j < 4; j++) D[mt][i][j] = 0.0f;

        const uint32_t bbase = su + P1_B + (uint32_t)buf * P1_BBUF;

        #pragma unroll
        for (int ks = 0; ks < 8; ks++) {
            uint32_t A_[2][4];
            {
                uint32_t ag = (uint32_t)(ks * 2 + akg);
                uint32_t asw = ((ag ^ arsw0) << 4);
                #pragma unroll
                for (int mt = 0; mt < 2; mt++)
                    ldsm_x4(A_[mt], abase[mt] + asw);
            }
            uint32_t B_[2][4];
            #pragma unroll
            for (int pp = 0; pp < 2; pp++) {
                int r  = pp * 16 + brow_local;
                int kg = ks * 2 + bkg_half;
                uint32_t bad = bbase + (uint32_t)r * 256u + ((uint32_t)(kg ^ (r & 7)) << 4);
                ldsm_x4(B_[pp], bad);
            }
            #pragma unroll
            for (int mt = 0; mt < 2; mt++)
                #pragma unroll
                for (int pp = 0; pp < 2; pp++) {
                    mma_f16(D[mt][pp * 2 + 0], A_[mt], B_[pp][0], B_[pp][1]);
                    mma_f16(D[mt][pp * 2 + 1], A_[mt], B_[pp][2], B_[pp][3]);
                }
        }

        // fold with runner-up (ascending cluster order)
        #pragma unroll
        for (int nt = 0; nt < 4; nt++) {
            int cb = ch * CHW + nt * 8 + 2 * (lane & 3);
            float c20 = c2p[nt].x, c21 = c2p[nt].y;
            #pragma unroll
            for (int mt = 0; mt < 2; mt++)
                #pragma unroll
                for (int hf = 0; hf < 2; hf++) {
                    float v0 = (c20 + x2r[mt][hf]) + D[mt][nt][hf * 2 + 0];
                    float v1 = (c21 + x2r[mt][hf]) + D[mt][nt][hf * 2 + 1];
                    if (v0 < b1[mt][hf]) { b2[mt][hf] = b1[mt][hf]; b1[mt][hf] = v0; i1[mt][hf] = cb; }
                    else if (v0 < b2[mt][hf]) b2[mt][hf] = v0;
                    if (v1 < b1[mt][hf]) { b2[mt][hf] = b1[mt][hf]; b1[mt][hf] = v1; i1[mt][hf] = cb + 1; }
                    else if (v1 < b2[mt][hf]) b2[mt][hf] = v1;
                }
        }
    }

    // cross-lane 2-min merge over the 4 lanes sharing each point row
    #pragma unroll
    for (int off = 1; off < 4; off <<= 1) {
        #pragma unroll
        for (int mt = 0; mt < 2; mt++)
            #pragma unroll
            for (int hf = 0; hf < 2; hf++) {
                float o1 = __shfl_xor_sync(0xffffffffu, b1[mt][hf], off);
                int   oi = __shfl_xor_sync(0xffffffffu, i1[mt][hf], off);
                float o2 = __shfl_xor_sync(0xffffffffu, b2[mt][hf], off);
                float hi = fmaxf(b1[mt][hf], o1);
                b2[mt][hf] = fminf(fminf(b2[mt][hf], o2), hi);
                if (o1 < b1[mt][hf] || (o1 == b1[mt][hf] && oi < i1[mt][hf])) {
                    b1[mt][hf] = o1; i1[mt][hf] = oi;
                }
            }
    }

    if ((lane & 3) == 0) {
        #pragma unroll
        for (int mt = 0; mt < 2; mt++)
            #pragma unroll
            for (int hf = 0; hf < 2; hf++) {
                int rA = p0 + mt * 16 + hf * 8 + (lane >> 2);
                int n  = base + rA;
                if (n < NPTS) {
                    out_asg[n] = (float)i1[mt][hf];
                    if (!(b2[mt][hf] - b1[mt][hf] > thr[mt][hf])) {
                        int s = atomicAdd(&g_nflag, 1);
                        g_flagged[s] = n;
                    }
                }
            }
    }
}

// ================= phase 3: 3-pass refine on flagged points =================
// Identical math to the validated round-9/10 kernel; points via g_flagged.
#define P3_A_SPLIT 32768
#define P3_B       65536
#define P3_BBUF    16384
#define P3_BSPLIT  8192
#define P3_NBUF    3
#define P3_SM      (P3_B + P3_NBUF * P3_BBUF)   // 114688 -> 2 CTAs/SM

__device__ __forceinline__ void p3_issue_b(uint32_t su, int tid, int ch, int buf) {
    #pragma unroll
    for (int s = 0; s < 2; s++) {
        const __half* g = (s == 0) ? g_cent_hi : g_cent_mi;
        const char* gb = (const char*)(g + (size_t)ch * CHW * DIM);
        #pragma unroll
        for (int it = 0; it < 4; it++) {
            int idx = tid + it * THR;
            int row = idx >> 4, kg = idx & 15;
            uint32_t dst = su + P3_B + (uint32_t)buf * P3_BBUF
                         + (uint32_t)s * P3_BSPLIT + (uint32_t)row * 256u
                         + ((uint32_t)(kg ^ (row & 7)) << 4);
            cp16(dst, gb + (size_t)idx * 16);
        }
    }
    CP_COMMIT();
}

__global__ __launch_bounds__(THR, 2)
void phase3_kernel(const float* __restrict__ vecs, float* __restrict__ out_asg) {
    const int cnt = g_nflag;
    const int base = blockIdx.x * PTS_CTA;
    if (base >= cnt) return;

    extern __shared__ __align__(1024) char sm[];
    const uint32_t su = smem_u32(sm);
    const int tid  = threadIdx.x;
    const int lane = tid & 31;
    const int w    = tid >> 5;

    p3_issue_b(su, tid, 0, 0);
    p3_issue_b(su, tid, 1, 1);

    float s2tot;
    {
        int p = tid;
        int fi = base + p;
        int n = (fi < cnt) ? g_flagged[fi] : g_flagged[0];
        const uint32_t rowb = (uint32_t)p * 256u;
        const uint32_t psw  = (uint32_t)(p & 7);
        float s2h[2];
        #pragma unroll
        for (int h = 0; h < 2; h++) {
            const float4* src = (const float4*)(vecs + (size_t)n * DIM) + h * 16;
            float s2 = 0.0f;
            #pragma unroll
            for (int j = 0; j < 16; j++) {
                float4 v = src[j];
                int d0 = h * 64 + j * 4;
                #pragma unroll
                for (int q = 0; q < 2; q++) {
                    float a0 = q ? v.z : v.x;
                    float a1 = q ? v.w : v.y;
                    int   d  = d0 + 2 * q;
                    s2 = fmaf(a0, a0, s2); s2 = fmaf(a1, a1, s2);
                    __half h0 = __float2half_rn(a0);
                    __half m0 = __float2half_rn(a0 - __half2float(h0));
                    __half h1 = __float2half_rn(a1);
                    __half m1 = __float2half_rn(a1 - __half2float(h1));
                    uint32_t off = rowb + ((((uint32_t)(d >> 3)) ^ psw) << 4) + (uint32_t)(d & 7) * 2u;
                    __half2 ph(h0, h1), pm(m0, m1);
                    *(uint32_t*)(sm + 0 * P3_A_SPLIT + off) = *(uint32_t*)&ph;
                    *(uint32_t*)(sm + 1 * P3_A_SPLIT + off) = *(uint32_t*)&pm;
                }
            }
            s2h[h] = s2;
        }
        s2tot = s2h[0] + s2h[1];
    }
    __syncthreads();

    const int p0 = w * 32;
    float x2r[2][2];
    #pragma unroll
    for (int mt = 0; mt < 2; mt++)
        #pragma unroll
        for (int hf = 0; hf < 2; hf++)
            x2r[mt][hf] = __shfl_sync(0xffffffffu, s2tot, mt * 16 + hf * 8 + (lane >> 2));

    float best[2][2] = {{3.402823466e38f, 3.402823466e38f},
                        {3.402823466e38f, 3.402823466e38f}};
    int   bi[2][2]   = {{0, 0}, {0, 0}};

    uint32_t abase[2];
    #pragma unroll
    for (int mt = 0; mt < 2; mt++)
        abase[mt] = su + (uint32_t)(p0 + mt * 16 + (lane & 15)) * 256u;
    const uint32_t arsw0 = (uint32_t)((p0 + (lane & 15)) & 7);
    const int akg  = lane >> 4;
    const int brow_local = ((lane >> 4) << 3) + (lane & 7);
    const int bkg_half   = (lane >> 3) & 1;

    for (int ch = 0; ch < CH_N; ch++) {
        const int buf = ch % P3_NBUF;
        if (ch + 1 < CH_N) { CP_WAIT1(); } else { CP_WAIT0(); }
        __syncthreads();
        if (ch + 2 < CH_N) p3_issue_b(su, tid, ch + 2, (ch + 2) % P3_NBUF);

        float2 c2p[4];
        #pragma unroll
        for (int nt = 0; nt < 4; nt++)
            c2p[nt] = __ldg((const float2*)(g_c2 + ch * CHW + nt * 8 + 2 * (lane & 3)));

        float D[2][4][4];
        #pragma unroll
        for (int mt = 0; mt < 2; mt++)
            #pragma unroll
            for (int i = 0; i < 4; i++)
                #pragma unroll
                for (int j = 0; j < 4; j++) D[mt][i][j] = 0.0f;

        const uint32_t bbase = su + P3_B + (uint32_t)buf * P3_BBUF;

        #pragma unroll
        for (int ks = 0; ks < 8; ks++) {
            uint32_t A_[2][2][4];
            {
                uint32_t ag = (uint32_t)(ks * 2 + akg);
                uint32_t asw = ((ag ^ arsw0) << 4);
                #pragma unroll
                for (int mt = 0; mt < 2; mt++) {
                    ldsm_x4(A_[0][mt], abase[mt] + 0 * P3_A_SPLIT + asw);
                    ldsm_x4(A_[1][mt], abase[mt] + 1 * P3_A_SPLIT + asw);
                }
            }
            uint32_t B_[2][2][4];
            #pragma unroll
            for (int pp = 0; pp < 2; pp++) {
                int r  = pp * 16 + brow_local;
                int kg = ks * 2 + bkg_half;
                uint32_t bad = bbase + (uint32_t)r * 256u + ((uint32_t)(kg ^ (r & 7)) << 4);
                ldsm_x4(B_[0][pp], bad + 0 * P3_BSPLIT);
                ldsm_x4(B_[1][pp], bad + 1 * P3_BSPLIT);
            }
            const int SA[3] = {0, 0, 1};
            const int SB[3] = {0, 1, 0};
            #pragma unroll
            for (int p3 = 0; p3 < 3; p3++)
                #pragma unroll
                for (int mt = 0; mt < 2; mt++)
                    #pragma unroll
                    for (int pp = 0; pp < 2; pp++) {
                        mma_f16(D[mt][pp * 2 + 0], A_[SA[p3]][mt], B_[SB[p3]][pp][0], B_[SB[p3]][pp][1]);
                        mma_f16(D[mt][pp * 2 + 1], A_[SA[p3]][mt], B_[SB[p3]][pp][2], B_[SB[p3]][pp][3]);
                    }
        }

        #pragma unroll
        for (int nt = 0; nt < 4; nt++) {
            int cb = ch * CHW + nt * 8 + 2 * (lane & 3);
            float c20 = c2p[nt].x, c21 = c2p[nt].y;
            #pragma unroll
            for (int mt = 0; mt < 2; mt++) {
                float v;
                v = (c20 + x2r[mt][0]) + D[mt][nt][0]; if (v < best[mt][0]) { best[mt][0] = v; bi[mt][0] = cb; }
                v = (c21 + x2r[mt][0]) + D[mt][nt][1]; if (v < best[mt][0]) { best[mt][0] = v; bi[mt][0] = cb + 1; }
                v = (c20 + x2r[mt][1]) + D[mt][nt][2]; if (v < best[mt][1]) { best[mt][1] = v; bi[mt][1] = cb; }
                v = (c21 + x2r[mt][1]) + D[mt][nt][3]; if (v < best[mt][1]) { best[mt][1] = v; bi[mt][1] = cb + 1; }
            }
        }
    }

    #pragma unroll
    for (int off = 1; off < 4; off <<= 1) {
        #pragma unroll
        for (int mt = 0; mt < 2; mt++)
            #pragma unroll
            for (int hf = 0; hf < 2; hf++) {
                float ov = __shfl_xor_sync(0xffffffffu, best[mt][hf], off);
                int   oi = __shfl_xor_sync(0xffffffffu, bi[mt][hf],   off);
                if (ov < best[mt][hf] || (ov == best[mt][hf] && oi < bi[mt][hf])) {
                    best[mt][hf] = ov; bi[mt][hf] = oi;
                }
            }
    }
    if ((lane & 3) == 0) {
        #pragma unroll
        for (int mt = 0; mt < 2; mt++)
            #pragma unroll
            for (int hf = 0; hf < 2; hf++) {
                int rA = p0 + mt * 16 + hf * 8 + (lane >> 2);
                int fi = base + rA;
                if (fi < cnt) out_asg[g_flagged[fi]] = (float)bi[mt][hf];
            }
    }
}

// ---------------- launch ----------------
extern "C" void kernel_launch(void* const* d_in, const int* in_sizes, int n_in,
                              void* d_out, int out_size) {
    const float* vecs = (const float*)d_in[0];
    const int*   asg  = (const int*)d_in[1];
    float* out      = (float*)d_out;
    float* out_cent = out;             // [KC*DIM]
    float* out_asg  = out + KC * DIM;  // [NPTS]

    zero_kernel<<<(KC * DIM + 255) / 256, 256>>>();
    segsum_kernel<<<(NPTS * 32) / 256, 256>>>(vecs, asg);
    finalize_kernel<<<KC, DIM>>>(out_cent);

    int ablocks = (NPTS + PTS_CTA - 1) / PTS_CTA;
    cudaFuncSetAttribute(phase1_kernel,
                         cudaFuncAttributeMaxDynamicSharedMemorySize, P1_SM);
    phase1_kernel<<<ablocks, THR, P1_SM>>>(vecs, out_asg);

    cudaFuncSetAttribute(phase3_kernel,
                         cudaFuncAttributeMaxDynamicSharedMemorySize, P3_SM);
    phase3_kernel<<<ablocks, THR, P3_SM>>>(vecs, out_asg);
}

// round 14
// speedup vs baseline: 1.7102x; 1.2480x over previous
#include <cuda_runtime.h>
#include <cuda_fp16.h>
#include <cstdint>
#include <cstddef>

#define NPTS 500000
#define DIM  128
#define KC   1024

// ---------------- scratch ----------------
__device__ float g_sums[KC * DIM];
__device__ float g_counts[KC];
__device__ float g_c2[KC];
__device__ __half g_cent_hi[KC * DIM];   // fp16 splits of -2*centroid
__device__ __half g_cent_mi[KC * DIM];
__device__ int   g_flagged[NPTS];
__device__ int   g_nflag;
__device__ int   g_maxmh_bits;           // max over clusters of ||mh||  (float bits)
__device__ int   g_maxmm_bits;           // max over clusters of ||m - mh|| (float bits)

// ---------------- helpers ----------------
__device__ __forceinline__ uint32_t smem_u32(const void* p) {
    uint32_t a;
    asm("{ .reg .u64 t; cvta.to.shared.u64 t, %1; cvt.u32.u64 %0, t; }" : "=r"(a) : "l"(p));
    return a;
}
__device__ __forceinline__ void ldsm_x4(uint32_t* r, uint32_t addr) {
    asm volatile("ldmatrix.sync.aligned.m8n8.x4.shared.b16 {%0,%1,%2,%3}, [%4];"
        : "=r"(r[0]), "=r"(r[1]), "=r"(r[2]), "=r"(r[3]) : "r"(addr));
}
__device__ __forceinline__ void mma_f16(float* d, const uint32_t* a, uint32_t b0, uint32_t b1) {
    asm volatile("mma.sync.aligned.m16n8k16.row.col.f32.f16.f16.f32 "
        "{%0,%1,%2,%3}, {%4,%5,%6,%7}, {%8,%9}, {%0,%1,%2,%3};"
        : "+f"(d[0]), "+f"(d[1]), "+f"(d[2]), "+f"(d[3])
        : "r"(a[0]), "r"(a[1]), "r"(a[2]), "r"(a[3]), "r"(b0), "r"(b1));
}
__device__ __forceinline__ void cp16(uint32_t dst, const void* src) {
    asm volatile("cp.async.cg.shared.global [%0], [%1], 16;" :: "r"(dst), "l"(src) : "memory");
}
#define CP_COMMIT() asm volatile("cp.async.commit_group;" ::: "memory")
#define CP_WAIT0()  asm volatile("cp.async.wait_group 0;" ::: "memory")
#define CP_WAIT1()  asm volatile("cp.async.wait_group 1;" ::: "memory")

// ---------------- kernel 1: zero scratch ----------------
__global__ void zero_kernel() {
    int i = blockIdx.x * blockDim.x + threadIdx.x;
    if (i < KC * DIM) g_sums[i] = 0.0f;
    if (i < KC)       g_counts[i] = 0.0f;
    if (i == 0) { g_nflag = 0; g_maxmh_bits = 0; g_maxmm_bits = 0; }
}

// ---------------- kernel 2: segment sum ----------------
__global__ void segsum_kernel(const float* __restrict__ vecs,
                              const int*   __restrict__ asg) {
    int gw   = (blockIdx.x * blockDim.x + threadIdx.x) >> 5;
    int lane = threadIdx.x & 31;
    if (gw >= NPTS) return;
    int k = asg[gw];
    float4 v = *((const float4*)(vecs + (size_t)gw * DIM) + lane);
    atomicAdd(((float4*)(g_sums + (size_t)k * DIM)) + lane, v);
    if (lane == 0) atomicAdd(&g_counts[k], 1.0f);
}

// ---------------- kernel 3: centroids, c2, splits, split norms ----------------
__global__ void finalize_kernel(float* __restrict__ out_cent) {
    int k = blockIdx.x;
    int d = threadIdx.x;
    float c = g_sums[k * DIM + d] / g_counts[k];
    out_cent[k * DIM + d] = c;

    float m = -2.0f * c;
    __half h = __float2half_rn(m);
    float mhf = __half2float(h);
    float mmr = m - mhf;                      // residual beyond hh pass
    __half mi = __float2half_rn(mmr);
    g_cent_hi[k * DIM + d] = h;
    g_cent_mi[k * DIM + d] = mi;

    float s  = c * c;
    float sh = mhf * mhf;
    float sr = mmr * mmr;
    #pragma unroll
    for (int o = 16; o > 0; o >>= 1) {
        s  += __shfl_down_sync(0xffffffffu, s,  o);
        sh += __shfl_down_sync(0xffffffffu, sh, o);
        sr += __shfl_down_sync(0xffffffffu, sr, o);
    }
    __shared__ float ws[4], wh[4], wr[4];
    if ((d & 31) == 0) { ws[d >> 5] = s; wh[d >> 5] = sh; wr[d >> 5] = sr; }
    __syncthreads();
    if (d == 0) {
        g_c2[k] = (ws[0] + ws[1]) + (ws[2] + ws[3]);
        float nh = sqrtf((wh[0] + wh[1]) + (wh[2] + wh[3]));
        float nr = sqrtf((wr[0] + wr[1]) + (wr[2] + wr[3]));
        atomicMax(&g_maxmh_bits, __float_as_int(nh));   // norms >= 0
        atomicMax(&g_maxmm_bits, __float_as_int(nr));
    }
}

// ================= phase 1: hh-only MMA argmin + certification =================
// 128 points/CTA x 1024 clusters. 4 warps; warp w owns points 32w..32w+31.
// A: xh fp16, swizzled smem [128][256B]. B: mh, 32-cluster chunks, NBUF=3,
// issue-after-sync. Branch-free fold: 3-bit candidate index packed into low
// mantissa bits; top-2-of-8 FMNMX network per point-slot; one guarded global
// update per chunk. Certifies when (quantized) gap > thr.
#define PTS_CTA 128
#define THR     128
#define CH_N    32
#define CHW     32
#define P1_A    0
#define P1_B    32768
#define P1_BBUF 8192
#define P1_NBUF 3
#define P1_SM   (P1_B + P1_NBUF * P1_BBUF)    // 57344 -> 4 CTAs/SM

__device__ __forceinline__ void p1_issue_b(uint32_t su, int tid, int ch, int buf) {
    const char* gb = (const char*)(g_cent_hi + (size_t)ch * CHW * DIM);
    #pragma unroll
    for (int it = 0; it < 4; it++) {
        int idx = tid + it * THR;          // 0..511
        int row = idx >> 4, kg = idx & 15;
        uint32_t dst = su + P1_B + (uint32_t)buf * P1_BBUF + (uint32_t)row * 256u
                     + ((uint32_t)(kg ^ (row & 7)) << 4);
        cp16(dst, gb + (size_t)idx * 16);
    }
    CP_COMMIT();
}

__global__ __launch_bounds__(THR, 4)
void phase1_kernel(const float* __restrict__ vecs, float* __restrict__ out_asg) {
    extern __shared__ __align__(1024) char sm[];
    const uint32_t su = smem_u32(sm);
    const int tid  = threadIdx.x;
    const int lane = tid & 31;
    const int w    = tid >> 5;
    const int base = blockIdx.x * PTS_CTA;

    const float maxMh = __int_as_float(g_maxmh_bits);
    const float maxMm = __int_as_float(g_maxmm_bits);

    p1_issue_b(su, tid, 0, 0);
    p1_issue_b(su, tid, 1, 1);

    // A convert: fp32 -> xh fp16 (smem); x2 (frozen order), ||xh||^2, ||xmr||^2
    float s2tot, xh2, xmr2;
    {
        int p = tid;
        int n = base + p; if (n >= NPTS) n = NPTS - 1;
        const uint32_t rowb = (uint32_t)p * 256u;
        const uint32_t psw  = (uint32_t)(p & 7);
        float s2h[2]; xh2 = 0.0f; xmr2 = 0.0f;
        #pragma unroll
        for (int h = 0; h < 2; h++) {
            const float4* src = (const float4*)(vecs + (size_t)n * DIM) + h * 16;
            float s2 = 0.0f;
            #pragma unroll
            for (int j = 0; j < 16; j++) {
                float4 v = src[j];
                int d0 = h * 64 + j * 4;
                #pragma unroll
                for (int q = 0; q < 2; q++) {
                    float a0 = q ? v.z : v.x;
                    float a1 = q ? v.w : v.y;
                    int   d  = d0 + 2 * q;
                    s2 = fmaf(a0, a0, s2); s2 = fmaf(a1, a1, s2);
                    __half h0 = __float2half_rn(a0);
                    __half h1 = __float2half_rn(a1);
                    float f0 = __half2float(h0), f1 = __half2float(h1);
                    float r0 = a0 - f0, r1 = a1 - f1;
                    xh2  = fmaf(f0, f0, xh2);  xh2  = fmaf(f1, f1, xh2);
                    xmr2 = fmaf(r0, r0, xmr2); xmr2 = fmaf(r1, r1, xmr2);
                    uint32_t off = rowb + ((((uint32_t)(d >> 3)) ^ psw) << 4) + (uint32_t)(d & 7) * 2u;
                    __half2 ph(h0, h1);
                    *(uint32_t*)(sm + P1_A + off) = *(uint32_t*)&ph;
                }
            }
            s2h[h] = s2;
        }
        s2tot = s2h[0] + s2h[1];
    }

    const int p0 = w * 32;
    float x2r[2][2], thr[2][2];
    #pragma unroll
    for (int mt = 0; mt < 2; mt++)
        #pragma unroll
        for (int hf = 0; hf < 2; hf++) {
            int sl = mt * 16 + hf * 8 + (lane >> 2);
            x2r[mt][hf]  = __shfl_sync(0xffffffffu, s2tot, sl);
            float a2 = __shfl_sync(0xffffffffu, xmr2, sl);
            float h2 = __shfl_sync(0xffffffffu, xh2,  sl);
            // + 7e-4: 2e-4 accum slack + 5e-4 for 8-ulp index-pack quantization
            thr[mt][hf] = 3.0f * (sqrtf(a2) * (maxMh + maxMm) + sqrtf(h2) * maxMm) + 7e-4f;
        }

    float b1[2][2] = {{3.402823466e38f, 3.402823466e38f},
                      {3.402823466e38f, 3.402823466e38f}};
    float b2[2][2] = {{3.402823466e38f, 3.402823466e38f},
                      {3.402823466e38f, 3.402823466e38f}};
    int   i1[2][2] = {{0, 0}, {0, 0}};

    uint32_t abase[2];
    #pragma unroll
    for (int mt = 0; mt < 2; mt++)
        abase[mt] = su + P1_A + (uint32_t)(p0 + mt * 16 + (lane & 15)) * 256u;
    const uint32_t arsw0 = (uint32_t)((p0 + (lane & 15)) & 7);
    const int akg  = lane >> 4;
    const int brow_local = ((lane >> 4) << 3) + (lane & 7);
    const int bkg_half   = (lane >> 3) & 1;
    const int lidx4      = 2 * (lane & 3);

    for (int ch = 0; ch < CH_N; ch++) {
        const int buf = ch % P1_NBUF;
        if (ch + 1 < CH_N) { CP_WAIT1(); } else { CP_WAIT0(); }
        __syncthreads();
        if (ch + 2 < CH_N) p1_issue_b(su, tid, ch + 2, (ch + 2) % P1_NBUF);

        float2 c2p[4];
        #pragma unroll
        for (int nt = 0; nt < 4; nt++)
            c2p[nt] = __ldg((const float2*)(g_c2 + ch * CHW + nt * 8 + lidx4));

        float D[2][4][4];
        #pragma unroll
        for (int mt = 0; mt < 2; mt++)
            #pragma unroll
            for (int i = 0; i < 4; i++)
                #pragma unroll
                for (int j = 0; j < 4; j++) D[mt][i][j] = 0.0f;

        const uint32_t bbase = su + P1_B + (uint32_t)buf * P1_BBUF;

        #pragma unroll
        for (int ks = 0; ks < 8; ks++) {
            uint32_t A_[2][4];
            {
                uint32_t ag = (uint32_t)(ks * 2 + akg);
                uint32_t asw = ((ag ^ arsw0) << 4);
                #pragma unroll
                for (int mt = 0; mt < 2; mt++)
                    ldsm_x4(A_[mt], abase[mt] + asw);
            }
            uint32_t B_[2][4];
            #pragma unroll
            for (int pp = 0; pp < 2; pp++) {
                int r  = pp * 16 + brow_local;
                int kg = ks * 2 + bkg_half;
                uint32_t bad = bbase + (uint32_t)r * 256u + ((uint32_t)(kg ^ (r & 7)) << 4);
                ldsm_x4(B_[pp], bad);
            }
            #pragma unroll
            for (int mt = 0; mt < 2; mt++)
                #pragma unroll
                for (int pp = 0; pp < 2; pp++) {
                    mma_f16(D[mt][pp * 2 + 0], A_[mt], B_[pp][0], B_[pp][1]);
                    mma_f16(D[mt][pp * 2 + 1], A_[mt], B_[pp][2], B_[pp][3]);
                }
        }

        // ---- branch-free fold: pack 3-bit candidate idx, top-2-of-8 network ----
        #pragma unroll
        for (int mt = 0; mt < 2; mt++)
            #pragma unroll
            for (int hf = 0; hf < 2; hf++) {
                float pf[8];
                #pragma unroll
                for (int nt = 0; nt < 4; nt++) {
                    float v0 = (c2p[nt].x + x2r[mt][hf]) + D[mt][nt][hf * 2 + 0];
                    float v1 = (c2p[nt].y + x2r[mt][hf]) + D[mt][nt][hf * 2 + 1];
                    pf[nt * 2 + 0] = __uint_as_float((__float_as_uint(v0) & 0xFFFFFFF8u) | (uint32_t)(nt * 2 + 0));
                    pf[nt * 2 + 1] = __uint_as_float((__float_as_uint(v1) & 0xFFFFFFF8u) | (uint32_t)(nt * 2 + 1));
                }
                float a0 = fminf(pf[0], pf[1]), A0 = fmaxf(pf[0], pf[1]);
                float a1 = fminf(pf[2], pf[3]), A1 = fmaxf(pf[2], pf[3]);
                float a2 = fminf(pf[4], pf[5]), A2 = fmaxf(pf[4], pf[5]);
                float a3 = fminf(pf[6], pf[7]), A3 = fmaxf(pf[6], pf[7]);
                float m0 = fminf(a0, a1), s0 = fminf(fmaxf(a0, a1), fminf(A0, A1));
                float m1 = fminf(a2, a3), s1 = fminf(fmaxf(a2, a3), fminf(A2, A3));
                float M  = fminf(m0, m1), S  = fminf(fmaxf(m0, m1), fminf(s0, s1));
                b2[mt][hf] = fminf(fminf(b2[mt][hf], S), fmaxf(b1[mt][hf], M));
                if (M < b1[mt][hf]) {
                    uint32_t j = __float_as_uint(M) & 7u;
                    i1[mt][hf] = ch * CHW + (int)(((j >> 1) << 3) | (j & 1)) + lidx4;
                    b1[mt][hf] = M;
                }
            }
    }

    // cross-lane 2-min merge over the 4 lanes sharing each point row
    #pragma unroll
    for (int off = 1; off < 4; off <<= 1) {
        #pragma unroll
        for (int mt = 0; mt < 2; mt++)
            #pragma unroll
            for (int hf = 0; hf < 2; hf++) {
                float o1 = __shfl_xor_sync(0xffffffffu, b1[mt][hf], off);
                int   oi = __shfl_xor_sync(0xffffffffu, i1[mt][hf], off);
                float o2 = __shfl_xor_sync(0xffffffffu, b2[mt][hf], off);
                float hi = fmaxf(b1[mt][hf], o1);
                b2[mt][hf] = fminf(fminf(b2[mt][hf], o2), hi);
                if (o1 < b1[mt][hf] || (o1 == b1[mt][hf] && oi < i1[mt][hf])) {
                    b1[mt][hf] = o1; i1[mt][hf] = oi;
                }
            }
    }

    if ((lane & 3) == 0) {
        #pragma unroll
        for (int mt = 0; mt < 2; mt++)
            #pragma unroll
            for (int hf = 0; hf < 2; hf++) {
                int rA = p0 + mt * 16 + hf * 8 + (lane >> 2);
                int n  = base + rA;
                if (n < NPTS) {
                    out_asg[n] = (float)i1[mt][hf];
                    if (!(b2[mt][hf] - b1[mt][hf] > thr[mt][hf])) {
                        int s = atomicAdd(&g_nflag, 1);
                        g_flagged[s] = n;
                    }
                }
            }
    }
}

// ================= phase 3: 3-pass refine on flagged points =================
// Identical math to the validated round-9/10 kernel; points via g_flagged.
#define P3_A_SPLIT 32768
#define P3_B       65536
#define P3_BBUF    16384
#define P3_BSPLIT  8192
#define P3_NBUF    3
#define P3_SM      (P3_B + P3_NBUF * P3_BBUF)   // 114688 -> 2 CTAs/SM

__device__ __forceinline__ void p3_issue_b(uint32_t su, int tid, int ch, int buf) {
    #pragma unroll
    for (int s = 0; s < 2; s++) {
        const __half* g = (s == 0) ? g_cent_hi : g_cent_mi;
        const char* gb = (const char*)(g + (size_t)ch * CHW * DIM);
        #pragma unroll
        for (int it = 0; it < 4; it++) {
            int idx = tid + it * THR;
            int row = idx >> 4, kg = idx & 15;
            uint32_t dst = su + P3_B + (uint32_t)buf * P3_BBUF
                         + (uint32_t)s * P3_BSPLIT + (uint32_t)row * 256u
                         + ((uint32_t)(kg ^ (row & 7)) << 4);
            cp16(dst, gb + (size_t)idx * 16);
        }
    }
    CP_COMMIT();
}

__global__ __launch_bounds__(THR, 2)
void phase3_kernel(const float* __restrict__ vecs, float* __restrict__ out_asg) {
    const int cnt = g_nflag;
    const int base = blockIdx.x * PTS_CTA;
    if (base >= cnt) return;

    extern __shared__ __align__(1024) char sm[];
    const uint32_t su = smem_u32(sm);
    const int tid  = threadIdx.x;
    const int lane = tid & 31;
    const int w    = tid >> 5;

    p3_issue_b(su, tid, 0, 0);
    p3_issue_b(su, tid, 1, 1);

    float s2tot;
    {
        int p = tid;
        int fi = base + p;
        int n = (fi < cnt) ? g_flagged[fi] : g_flagged[0];
        const uint32_t rowb = (uint32_t)p * 256u;
        const uint32_t psw  = (uint32_t)(p & 7);
        float s2h[2];
        #pragma unroll
        for (int h = 0; h < 2; h++) {
            const float4* src = (const float4*)(vecs + (size_t)n * DIM) + h * 16;
            float s2 = 0.0f;
            #pragma unroll
            for (int j = 0; j < 16; j++) {
                float4 v = src[j];
                int d0 = h * 64 + j * 4;
                #pragma unroll
                for (int q = 0; q < 2; q++) {
                    float a0 = q ? v.z : v.x;
                    float a1 = q ? v.w : v.y;
                    int   d  = d0 + 2 * q;
                    s2 = fmaf(a0, a0, s2); s2 = fmaf(a1, a1, s2);
                    __half h0 = __float2half_rn(a0);
                    __half m0 = __float2half_rn(a0 - __half2float(h0));
                    __half h1 = __float2half_rn(a1);
                    __half m1 = __float2half_rn(a1 - __half2float(h1));
                    uint32_t off = rowb + ((((uint32_t)(d >> 3)) ^ psw) << 4) + (uint32_t)(d & 7) * 2u;
                    __half2 ph(h0, h1), pm(m0, m1);
                    *(uint32_t*)(sm + 0 * P3_A_SPLIT + off) = *(uint32_t*)&ph;
                    *(uint32_t*)(sm + 1 * P3_A_SPLIT + off) = *(uint32_t*)&pm;
                }
            }
            s2h[h] = s2;
        }
        s2tot = s2h[0] + s2h[1];
    }
    __syncthreads();

    const int p0 = w * 32;
    float x2r[2][2];
    #pragma unroll
    for (int mt = 0; mt < 2; mt++)
        #pragma unroll
        for (int hf = 0; hf < 2; hf++)
            x2r[mt][hf] = __shfl_sync(0xffffffffu, s2tot, mt * 16 + hf * 8 + (lane >> 2));

    float best[2][2] = {{3.402823466e38f, 3.402823466e38f},
                        {3.402823466e38f, 3.402823466e38f}};
    int   bi[2][2]   = {{0, 0}, {0, 0}};

    uint32_t abase[2];
    #pragma unroll
    for (int mt = 0; mt < 2; mt++)
        abase[mt] = su + (uint32_t)(p0 + mt * 16 + (lane & 15)) * 256u;
    const uint32_t arsw0 = (uint32_t)((p0 + (lane & 15)) & 7);
    const int akg  = lane >> 4;
    const int brow_local = ((lane >> 4) << 3) + (lane & 7);
    const int bkg_half   = (lane >> 3) & 1;

    for (int ch = 0; ch < CH_N; ch++) {
        const int buf = ch % P3_NBUF;
        if (ch + 1 < CH_N) { CP_WAIT1(); } else { CP_WAIT0(); }
        __syncthreads();
        if (ch + 2 < CH_N) p3_issue_b(su, tid, ch + 2, (ch + 2) % P3_NBUF);

        float2 c2p[4];
        #pragma unroll
        for (int nt = 0; nt < 4; nt++)
            c2p[nt] = __ldg((const float2*)(g_c2 + ch * CHW + nt * 8 + 2 * (lane & 3)));

        float D[2][4][4];
        #pragma unroll
        for (int mt = 0; mt < 2; mt++)
            #pragma unroll
            for (int i = 0; i < 4; i++)
                #pragma unroll
                for (int j = 0; j < 4; j++) D[mt][i][j] = 0.0f;

        const uint32_t bbase = su + P3_B + (uint32_t)buf * P3_BBUF;

        #pragma unroll
        for (int ks = 0; ks < 8; ks++) {
            uint32_t A_[2][2][4];
            {
                uint32_t ag = (uint32_t)(ks * 2 + akg);
                uint32_t asw = ((ag ^ arsw0) << 4);
                #pragma unroll
                for (int mt = 0; mt < 2; mt++) {
                    ldsm_x4(A_[0][mt], abase[mt] + 0 * P3_A_SPLIT + asw);
                    ldsm_x4(A_[1][mt], abase[mt] + 1 * P3_A_SPLIT + asw);
                }
            }
            uint32_t B_[2][2][4];
            #pragma unroll
            for (int pp = 0; pp < 2; pp++) {
                int r  = pp * 16 + brow_local;
                int kg = ks * 2 + bkg_half;
                uint32_t bad = bbase + (uint32_t)r * 256u + ((uint32_t)(kg ^ (r & 7)) << 4);
                ldsm_x4(B_[0][pp], bad + 0 * P3_BSPLIT);
                ldsm_x4(B_[1][pp], bad + 1 * P3_BSPLIT);
            }
            const int SA[3] = {0, 0, 1};
            const int SB[3] = {0, 1, 0};
            #pragma unroll
            for (int p3 = 0; p3 < 3; p3++)
                #pragma unroll
                for (int mt = 0; mt < 2; mt++)
                    #pragma unroll
                    for (int pp = 0; pp < 2; pp++) {
                        mma_f16(D[mt][pp * 2 + 0], A_[SA[p3]][mt], B_[SB[p3]][pp][0], B_[SB[p3]][pp][1]);
                        mma_f16(D[mt][pp * 2 + 1], A_[SA[p3]][mt], B_[SB[p3]][pp][2], B_[SB[p3]][pp][3]);
                    }
        }

        #pragma unroll
        for (int nt = 0; nt < 4; nt++) {
            int cb = ch * CHW + nt * 8 + 2 * (lane & 3);
            float c20 = c2p[nt].x, c21 = c2p[nt].y;
            #pragma unroll
            for (int mt = 0; mt < 2; mt++) {
                float v;
                v = (c20 + x2r[mt][0]) + D[mt][nt][0]; if (v < best[mt][0]) { best[mt][0] = v; bi[mt][0] = cb; }
                v = (c21 + x2r[mt][0]) + D[mt][nt][1]; if (v < best[mt][0]) { best[mt][0] = v; bi[mt][0] = cb + 1; }
                v = (c20 + x2r[mt][1]) + D[mt][nt][2]; if (v < best[mt][1]) { best[mt][1] = v; bi[mt][1] = cb; }
                v = (c21 + x2r[mt][1]) + D[mt][nt][3]; if (v < best[mt][1]) { best[mt][1] = v; bi[mt][1] = cb + 1; }
            }
        }
    }

    #pragma unroll
    for (int off = 1; off < 4; off <<= 1) {
        #pragma unroll
        for (int mt = 0; mt < 2; mt++)
            #pragma unroll
            for (int hf = 0; hf < 2; hf++) {
                float ov = __shfl_xor_sync(0xffffffffu, best[mt][hf], off);
                int   oi = __shfl_xor_sync(0xffffffffu, bi[mt][hf],   off);
                if (ov < best[mt][hf] || (ov == best[mt][hf] && oi < bi[mt][hf])) {
                    best[mt][hf] = ov; bi[mt][hf] = oi;
                }
            }
    }
    if ((lane & 3) == 0) {
        #pragma unroll
        for (int mt = 0; mt < 2; mt++)
            #pragma unroll
            for (int hf = 0; hf < 2; hf++) {
                int rA = p0 + mt * 16 + hf * 8 + (lane >> 2);
                int fi = base + rA;
                if (fi < cnt) out_asg[g_flagged[fi]] = (float)bi[mt][hf];
            }
    }
}

// ---------------- launch ----------------
extern "C" void kernel_launch(void* const* d_in, const int* in_sizes, int n_in,
                              void* d_out, int out_size) {
    const float* vecs = (const float*)d_in[0];
    const int*   asg  = (const int*)d_in[1];
    float* out      = (float*)d_out;
    float* out_cent = out;             // [KC*DIM]
    float* out_asg  = out + KC * DIM;  // [NPTS]

    zero_kernel<<<(KC * DIM + 255) / 256, 256>>>();
    segsum_kernel<<<(NPTS * 32) / 256, 256>>>(vecs, asg);
    finalize_kernel<<<KC, DIM>>>(out_cent);

    int ablocks = (NPTS + PTS_CTA - 1) / PTS_CTA;
    cudaFuncSetAttribute(phase1_kernel,
                         cudaFuncAttributeMaxDynamicSharedMemorySize, P1_SM);
    phase1_kernel<<<ablocks, THR, P1_SM>>>(vecs, out_asg);

    cudaFuncSetAttribute(phase3_kernel,
                         cudaFuncAttributeMaxDynamicSharedMemorySize, P3_SM);
    phase3_kernel<<<ablocks, THR, P3_SM>>>(vecs, out_asg);
}

// round 15
// speedup vs baseline: 1.7234x; 1.0077x over previous
#include <cuda_runtime.h>
#include <cuda_fp16.h>
#include <cstdint>
#include <cstddef>

#define NPTS 500000
#define DIM  128
#define KC   1024

// ---------------- scratch ----------------
__device__ float g_sums[KC * DIM];
__device__ float g_counts[KC];
__device__ float g_c2[KC];
__device__ __half g_cent_hi[KC * DIM];   // fp16 splits of -2*centroid
__device__ __half g_cent_mi[KC * DIM];
__device__ int   g_flagged[NPTS];
__device__ int   g_nflag;
__device__ int   g_maxmh_bits;           // max over clusters of ||mh||  (float bits)
__device__ int   g_maxmm_bits;           // max over clusters of ||m - mh|| (float bits)

// ---------------- helpers ----------------
__device__ __forceinline__ uint32_t smem_u32(const void* p) {
    uint32_t a;
    asm("{ .reg .u64 t; cvta.to.shared.u64 t, %1; cvt.u32.u64 %0, t; }" : "=r"(a) : "l"(p));
    return a;
}
__device__ __forceinline__ void ldsm_x4(uint32_t* r, uint32_t addr) {
    asm volatile("ldmatrix.sync.aligned.m8n8.x4.shared.b16 {%0,%1,%2,%3}, [%4];"
        : "=r"(r[0]), "=r"(r[1]), "=r"(r[2]), "=r"(r[3]) : "r"(addr));
}
__device__ __forceinline__ void mma_f16(float* d, const uint32_t* a, uint32_t b0, uint32_t b1) {
    asm volatile("mma.sync.aligned.m16n8k16.row.col.f32.f16.f16.f32 "
        "{%0,%1,%2,%3}, {%4,%5,%6,%7}, {%8,%9}, {%0,%1,%2,%3};"
        : "+f"(d[0]), "+f"(d[1]), "+f"(d[2]), "+f"(d[3])
        : "r"(a[0]), "r"(a[1]), "r"(a[2]), "r"(a[3]), "r"(b0), "r"(b1));
}
__device__ __forceinline__ void cp16(uint32_t dst, const void* src) {
    asm volatile("cp.async.cg.shared.global [%0], [%1], 16;" :: "r"(dst), "l"(src) : "memory");
}
#define CP_COMMIT() asm volatile("cp.async.commit_group;" ::: "memory")
#define CP_WAIT0()  asm volatile("cp.async.wait_group 0;" ::: "memory")
#define CP_WAIT1()  asm volatile("cp.async.wait_group 1;" ::: "memory")

// ---------------- kernel 1: zero scratch ----------------
__global__ void zero_kernel() {
    int i = blockIdx.x * blockDim.x + threadIdx.x;
    if (i < KC * DIM) g_sums[i] = 0.0f;
    if (i < KC)       g_counts[i] = 0.0f;
    if (i == 0) { g_nflag = 0; g_maxmh_bits = 0; g_maxmm_bits = 0; }
}

// ---------------- kernel 2: segment sum ----------------
__global__ void segsum_kernel(const float* __restrict__ vecs,
                              const int*   __restrict__ asg) {
    int gw   = (blockIdx.x * blockDim.x + threadIdx.x) >> 5;
    int lane = threadIdx.x & 31;
    if (gw >= NPTS) return;
    int k = asg[gw];
    float4 v = *((const float4*)(vecs + (size_t)gw * DIM) + lane);
    atomicAdd(((float4*)(g_sums + (size_t)k * DIM)) + lane, v);
    if (lane == 0) atomicAdd(&g_counts[k], 1.0f);
}

// ---------------- kernel 3: centroids, c2, splits, split norms ----------------
__global__ void finalize_kernel(float* __restrict__ out_cent) {
    int k = blockIdx.x;
    int d = threadIdx.x;
    float c = g_sums[k * DIM + d] / g_counts[k];
    out_cent[k * DIM + d] = c;

    float m = -2.0f * c;
    __half h = __float2half_rn(m);
    float mhf = __half2float(h);
    float mmr = m - mhf;
    __half mi = __float2half_rn(mmr);
    g_cent_hi[k * DIM + d] = h;
    g_cent_mi[k * DIM + d] = mi;

    float s  = c * c;
    float sh = mhf * mhf;
    float sr = mmr * mmr;
    #pragma unroll
    for (int o = 16; o > 0; o >>= 1) {
        s  += __shfl_down_sync(0xffffffffu, s,  o);
        sh += __shfl_down_sync(0xffffffffu, sh, o);
        sr += __shfl_down_sync(0xffffffffu, sr, o);
    }
    __shared__ float ws[4], wh[4], wr[4];
    if ((d & 31) == 0) { ws[d >> 5] = s; wh[d >> 5] = sh; wr[d >> 5] = sr; }
    __syncthreads();
    if (d == 0) {
        g_c2[k] = (ws[0] + ws[1]) + (ws[2] + ws[3]);
        float nh = sqrtf((wh[0] + wh[1]) + (wh[2] + wh[3]));
        float nr = sqrtf((wr[0] + wr[1]) + (wr[2] + wr[3]));
        atomicMax(&g_maxmh_bits, __float_as_int(nh));
        atomicMax(&g_maxmm_bits, __float_as_int(nr));
    }
}

// ================= phase 1: hh-only MMA argmin + certification =================
// 128 points/CTA x 1024 clusters. 4 warps; warp w owns points 32w..32w+31.
// CHW=64 chunks (16 total): per k-step 6 LDSM / 16 MMA (ratio 0.375).
// Surrogate distance = c2 + D (x2 dropped; argmin-invariant, slack covers
// rounding asymmetry). Fold of chunk ch runs after chunk ch+1's barrier
// (registers survive; D folded before being overwritten). Top-2-of-16
// FMNMX network with 4-bit packed candidate index.
#define PTS_CTA 128
#define THR     128
#define P1_CHN  16
#define P1_CHW  64
#define P1_A    0
#define P1_B    32768
#define P1_BBUF 16384
#define P1_NBUF 3
#define P1_SM   (P1_B + P1_NBUF * P1_BBUF)    // 81920 -> 2 CTAs/SM

__device__ __forceinline__ void p1_issue_b(uint32_t su, int tid, int ch, int buf) {
    const char* gb = (const char*)(g_cent_hi + (size_t)ch * P1_CHW * DIM);
    #pragma unroll
    for (int it = 0; it < 8; it++) {
        int idx = tid + it * THR;          // 0..1023
        int row = idx >> 4, kg = idx & 15; // row 0..63
        uint32_t dst = su + P1_B + (uint32_t)buf * P1_BBUF + (uint32_t)row * 256u
                     + ((uint32_t)(kg ^ (row & 7)) << 4);
        cp16(dst, gb + (size_t)idx * 16);
    }
    CP_COMMIT();
}

__global__ __launch_bounds__(THR, 2)
void phase1_kernel(const float* __restrict__ vecs, float* __restrict__ out_asg) {
    extern __shared__ __align__(1024) char sm[];
    const uint32_t su = smem_u32(sm);
    const int tid  = threadIdx.x;
    const int lane = tid & 31;
    const int w    = tid >> 5;
    const int base = blockIdx.x * PTS_CTA;

    const float maxMh = __int_as_float(g_maxmh_bits);
    const float maxMm = __int_as_float(g_maxmm_bits);

    p1_issue_b(su, tid, 0, 0);
    p1_issue_b(su, tid, 1, 1);

    // A convert: fp32 -> xh fp16 (smem); ||xh||^2, ||xmr||^2 for the bound
    float xh2 = 0.0f, xmr2 = 0.0f;
    {
        int p = tid;
        int n = base + p; if (n >= NPTS) n = NPTS - 1;
        const uint32_t rowb = (uint32_t)p * 256u;
        const uint32_t psw  = (uint32_t)(p & 7);
        const float4* src = (const float4*)(vecs + (size_t)n * DIM);
        #pragma unroll
        for (int j = 0; j < 32; j++) {
            float4 v = src[j];
            int d0 = j * 4;
            #pragma unroll
            for (int q = 0; q < 2; q++) {
                float a0 = q ? v.z : v.x;
                float a1 = q ? v.w : v.y;
                int   d  = d0 + 2 * q;
                __half h0 = __float2half_rn(a0);
                __half h1 = __float2half_rn(a1);
                float f0 = __half2float(h0), f1 = __half2float(h1);
                float r0 = a0 - f0, r1 = a1 - f1;
                xh2  = fmaf(f0, f0, xh2);  xh2  = fmaf(f1, f1, xh2);
                xmr2 = fmaf(r0, r0, xmr2); xmr2 = fmaf(r1, r1, xmr2);
                uint32_t off = rowb + ((((uint32_t)(d >> 3)) ^ psw) << 4) + (uint32_t)(d & 7) * 2u;
                __half2 ph(h0, h1);
                *(uint32_t*)(sm + P1_A + off) = *(uint32_t*)&ph;
            }
        }
    }

    const int p0 = w * 32;
    float thr[2][2];
    #pragma unroll
    for (int mt = 0; mt < 2; mt++)
        #pragma unroll
        for (int hf = 0; hf < 2; hf++) {
            int sl = mt * 16 + hf * 8 + (lane >> 2);
            float a2 = __shfl_sync(0xffffffffu, xmr2, sl);
            float h2 = __shfl_sync(0xffffffffu, xh2,  sl);
            // 1.5e-3 additive: accum slack + 16-ulp index quantization
            // + x2-drop rounding asymmetry (all with >=2x margin)
            thr[mt][hf] = 3.0f * (sqrtf(a2) * (maxMh + maxMm) + sqrtf(h2) * maxMm) + 1.5e-3f;
        }

    float b1[2][2] = {{3.402823466e38f, 3.402823466e38f},
                      {3.402823466e38f, 3.402823466e38f}};
    float b2[2][2] = {{3.402823466e38f, 3.402823466e38f},
                      {3.402823466e38f, 3.402823466e38f}};
    int   i1[2][2] = {{0, 0}, {0, 0}};

    uint32_t abase[2];
    #pragma unroll
    for (int mt = 0; mt < 2; mt++)
        abase[mt] = su + P1_A + (uint32_t)(p0 + mt * 16 + (lane & 15)) * 256u;
    const uint32_t arsw0 = (uint32_t)((p0 + (lane & 15)) & 7);
    const int akg  = lane >> 4;
    const int brow_local = ((lane >> 4) << 3) + (lane & 7);
    const int bkg_half   = (lane >> 3) & 1;
    const int lidx4      = 2 * (lane & 3);

    float D[2][8][4];
    float2 c2p[8];

    for (int ch = 0; ch < P1_CHN; ch++) {
        const int buf = ch % P1_NBUF;
        if (ch + 1 < P1_CHN) { CP_WAIT1(); } else { CP_WAIT0(); }
        __syncthreads();
        if (ch + 2 < P1_CHN) p1_issue_b(su, tid, ch + 2, (ch + 2) % P1_NBUF);

        // ---- fold PREVIOUS chunk (registers only; overlaps cp.async/LDSM) ----
        if (ch > 0) {
            const int fch = ch - 1;
            #pragma unroll
            for (int mt = 0; mt < 2; mt++)
                #pragma unroll
                for (int hf = 0; hf < 2; hf++) {
                    float pf[16];
                    #pragma unroll
                    for (int nt = 0; nt < 8; nt++) {
                        float v0 = c2p[nt].x + D[mt][nt][hf * 2 + 0];
                        float v1 = c2p[nt].y + D[mt][nt][hf * 2 + 1];
                        pf[nt * 2 + 0] = __uint_as_float((__float_as_uint(v0) & 0xFFFFFFF0u) | (uint32_t)(nt * 2 + 0));
                        pf[nt * 2 + 1] = __uint_as_float((__float_as_uint(v1) & 0xFFFFFFF0u) | (uint32_t)(nt * 2 + 1));
                    }
                    float mn[8], mx[8];
                    #pragma unroll
                    for (int i = 0; i < 8; i++) {
                        mn[i] = fminf(pf[2 * i], pf[2 * i + 1]);
                        mx[i] = fmaxf(pf[2 * i], pf[2 * i + 1]);
                    }
                    float a0 = fminf(mn[0], mn[1]), A0 = fmaxf(mn[0], mn[1]);
                    float a1 = fminf(mn[2], mn[3]), A1 = fmaxf(mn[2], mn[3]);
                    float a2 = fminf(mn[4], mn[5]), A2 = fmaxf(mn[4], mn[5]);
                    float a3 = fminf(mn[6], mn[7]), A3 = fmaxf(mn[6], mn[7]);
                    float m0 = fminf(a0, a1), s0 = fminf(fmaxf(a0, a1), fminf(A0, A1));
                    float m1 = fminf(a2, a3), s1 = fminf(fmaxf(a2, a3), fminf(A2, A3));
                    float WIN = fminf(m0, m1);
                    float S_m = fminf(fmaxf(m0, m1), fminf(s0, s1));
                    float mM = fminf(fminf(fminf(mx[0], mx[1]), fminf(mx[2], mx[3])),
                                     fminf(fminf(mx[4], mx[5]), fminf(mx[6], mx[7])));
                    float S = fminf(S_m, mM);
                    b2[mt][hf] = fminf(fminf(b2[mt][hf], S), fmaxf(b1[mt][hf], WIN));
                    if (WIN < b1[mt][hf]) {
                        uint32_t j = __float_as_uint(WIN) & 15u;
                        i1[mt][hf] = fch * P1_CHW + (int)(((j >> 1) << 3) | (j & 1)) + lidx4;
                        b1[mt][hf] = WIN;
                    }
                }
        }

        // prefetch c2 for THIS chunk (consumed by next iteration's fold)
        #pragma unroll
        for (int nt = 0; nt < 8; nt++)
            c2p[nt] = __ldg((const float2*)(g_c2 + ch * P1_CHW + nt * 8 + lidx4));

        #pragma unroll
        for (int mt = 0; mt < 2; mt++)
            #pragma unroll
            for (int i = 0; i < 8; i++)
                #pragma unroll
                for (int j = 0; j < 4; j++) D[mt][i][j] = 0.0f;

        const uint32_t bbase = su + P1_B + (uint32_t)buf * P1_BBUF;

        #pragma unroll
        for (int ks = 0; ks < 8; ks++) {
            uint32_t A_[2][4];
            {
                uint32_t ag = (uint32_t)(ks * 2 + akg);
                uint32_t asw = ((ag ^ arsw0) << 4);
                #pragma unroll
                for (int mt = 0; mt < 2; mt++)
                    ldsm_x4(A_[mt], abase[mt] + asw);
            }
            uint32_t B_[4][4];
            #pragma unroll
            for (int pp = 0; pp < 4; pp++) {
                int r  = pp * 16 + brow_local;
                int kg = ks * 2 + bkg_half;
                uint32_t bad = bbase + (uint32_t)r * 256u + ((uint32_t)(kg ^ (r & 7)) << 4);
                ldsm_x4(B_[pp], bad);
            }
            #pragma unroll
            for (int mt = 0; mt < 2; mt++)
                #pragma unroll
                for (int pp = 0; pp < 4; pp++) {
                    mma_f16(D[mt][pp * 2 + 0], A_[mt], B_[pp][0], B_[pp][1]);
                    mma_f16(D[mt][pp * 2 + 1], A_[mt], B_[pp][2], B_[pp][3]);
                }
        }
    }

    // ---- final fold (last chunk) ----
    {
        const int fch = P1_CHN - 1;
        #pragma unroll
        for (int mt = 0; mt < 2; mt++)
            #pragma unroll
            for (int hf = 0; hf < 2; hf++) {
                float pf[16];
                #pragma unroll
                for (int nt = 0; nt < 8; nt++) {
                    float v0 = c2p[nt].x + D[mt][nt][hf * 2 + 0];
                    float v1 = c2p[nt].y + D[mt][nt][hf * 2 + 1];
                    pf[nt * 2 + 0] = __uint_as_float((__float_as_uint(v0) & 0xFFFFFFF0u) | (uint32_t)(nt * 2 + 0));
                    pf[nt * 2 + 1] = __uint_as_float((__float_as_uint(v1) & 0xFFFFFFF0u) | (uint32_t)(nt * 2 + 1));
                }
                float mn[8], mx[8];
                #pragma unroll
                for (int i = 0; i < 8; i++) {
                    mn[i] = fminf(pf[2 * i], pf[2 * i + 1]);
                    mx[i] = fmaxf(pf[2 * i], pf[2 * i + 1]);
                }
                float a0 = fminf(mn[0], mn[1]), A0 = fmaxf(mn[0], mn[1]);
                float a1 = fminf(mn[2], mn[3]), A1 = fmaxf(mn[2], mn[3]);
                float a2 = fminf(mn[4], mn[5]), A2 = fmaxf(mn[4], mn[5]);
                float a3 = fminf(mn[6], mn[7]), A3 = fmaxf(mn[6], mn[7]);
                float m0 = fminf(a0, a1), s0 = fminf(fmaxf(a0, a1), fminf(A0, A1));
                float m1 = fminf(a2, a3), s1 = fminf(fmaxf(a2, a3), fminf(A2, A3));
                float WIN = fminf(m0, m1);
                float S_m = fminf(fmaxf(m0, m1), fminf(s0, s1));
                float mM = fminf(fminf(fminf(mx[0], mx[1]), fminf(mx[2], mx[3])),
                                 fminf(fminf(mx[4], mx[5]), fminf(mx[6], mx[7])));
                float S = fminf(S_m, mM);
                b2[mt][hf] = fminf(fminf(b2[mt][hf], S), fmaxf(b1[mt][hf], WIN));
                if (WIN < b1[mt][hf]) {
                    uint32_t j = __float_as_uint(WIN) & 15u;
                    i1[mt][hf] = fch * P1_CHW + (int)(((j >> 1) << 3) | (j & 1)) + lidx4;
                    b1[mt][hf] = WIN;
                }
            }
    }

    // cross-lane 2-min merge over the 4 lanes sharing each point row
    #pragma unroll
    for (int off = 1; off < 4; off <<= 1) {
        #pragma unroll
        for (int mt = 0; mt < 2; mt++)
            #pragma unroll
            for (int hf = 0; hf < 2; hf++) {
                float o1 = __shfl_xor_sync(0xffffffffu, b1[mt][hf], off);
                int   oi = __shfl_xor_sync(0xffffffffu, i1[mt][hf], off);
                float o2 = __shfl_xor_sync(0xffffffffu, b2[mt][hf], off);
                float hi = fmaxf(b1[mt][hf], o1);
                b2[mt][hf] = fminf(fminf(b2[mt][hf], o2), hi);
                if (o1 < b1[mt][hf] || (o1 == b1[mt][hf] && oi < i1[mt][hf])) {
                    b1[mt][hf] = o1; i1[mt][hf] = oi;
                }
            }
    }

    if ((lane & 3) == 0) {
        #pragma unroll
        for (int mt = 0; mt < 2; mt++)
            #pragma unroll
            for (int hf = 0; hf < 2; hf++) {
                int rA = p0 + mt * 16 + hf * 8 + (lane >> 2);
                int n  = base + rA;
                if (n < NPTS) {
                    out_asg[n] = (float)i1[mt][hf];
                    if (!(b2[mt][hf] - b1[mt][hf] > thr[mt][hf])) {
                        int s = atomicAdd(&g_nflag, 1);
                        g_flagged[s] = n;
                    }
                }
            }
    }
}

// ================= phase 3: 3-pass refine on flagged points =================
// Identical math to the validated round-9/10 kernel; points via g_flagged.
#define P3_CHN     32
#define P3_CHW     32
#define P3_A_SPLIT 32768
#define P3_B       65536
#define P3_BBUF    16384
#define P3_BSPLIT  8192
#define P3_NBUF    3
#define P3_SM      (P3_B + P3_NBUF * P3_BBUF)   // 114688 -> 2 CTAs/SM

__device__ __forceinline__ void p3_issue_b(uint32_t su, int tid, int ch, int buf) {
    #pragma unroll
    for (int s = 0; s < 2; s++) {
        const __half* g = (s == 0) ? g_cent_hi : g_cent_mi;
        const char* gb = (const char*)(g + (size_t)ch * P3_CHW * DIM);
        #pragma unroll
        for (int it = 0; it < 4; it++) {
            int idx = tid + it * THR;
            int row = idx >> 4, kg = idx & 15;
            uint32_t dst = su + P3_B + (uint32_t)buf * P3_BBUF
                         + (uint32_t)s * P3_BSPLIT + (uint32_t)row * 256u
                         + ((uint32_t)(kg ^ (row & 7)) << 4);
            cp16(dst, gb + (size_t)idx * 16);
        }
    }
    CP_COMMIT();
}

__global__ __launch_bounds__(THR, 2)
void phase3_kernel(const float* __restrict__ vecs, float* __restrict__ out_asg) {
    const int cnt = g_nflag;
    const int base = blockIdx.x * PTS_CTA;
    if (base >= cnt) return;

    extern __shared__ __align__(1024) char sm[];
    const uint32_t su = smem_u32(sm);
    const int tid  = threadIdx.x;
    const int lane = tid & 31;
    const int w    = tid >> 5;

    p3_issue_b(su, tid, 0, 0);
    p3_issue_b(su, tid, 1, 1);

    float s2tot;
    {
        int p = tid;
        int fi = base + p;
        int n = (fi < cnt) ? g_flagged[fi] : g_flagged[0];
        const uint32_t rowb = (uint32_t)p * 256u;
        const uint32_t psw  = (uint32_t)(p & 7);
        float s2h[2];
        #pragma unroll
        for (int h = 0; h < 2; h++) {
            const float4* src = (const float4*)(vecs + (size_t)n * DIM) + h * 16;
            float s2 = 0.0f;
            #pragma unroll
            for (int j = 0; j < 16; j++) {
                float4 v = src[j];
                int d0 = h * 64 + j * 4;
                #pragma unroll
                for (int q = 0; q < 2; q++) {
                    float a0 = q ? v.z : v.x;
                    float a1 = q ? v.w : v.y;
                    int   d  = d0 + 2 * q;
                    s2 = fmaf(a0, a0, s2); s2 = fmaf(a1, a1, s2);
                    __half h0 = __float2half_rn(a0);
                    __half m0 = __float2half_rn(a0 - __half2float(h0));
                    __half h1 = __float2half_rn(a1);
                    __half m1 = __float2half_rn(a1 - __half2float(h1));
                    uint32_t off = rowb + ((((uint32_t)(d >> 3)) ^ psw) << 4) + (uint32_t)(d & 7) * 2u;
                    __half2 ph(h0, h1), pm(m0, m1);
                    *(uint32_t*)(sm + 0 * P3_A_SPLIT + off) = *(uint32_t*)&ph;
                    *(uint32_t*)(sm + 1 * P3_A_SPLIT + off) = *(uint32_t*)&pm;
                }
            }
            s2h[h] = s2;
        }
        s2tot = s2h[0] + s2h[1];
    }
    __syncthreads();

    const int p0 = w * 32;
    float x2r[2][2];
    #pragma unroll
    for (int mt = 0; mt < 2; mt++)
        #pragma unroll
        for (int hf = 0; hf < 2; hf++)
            x2r[mt][hf] = __shfl_sync(0xffffffffu, s2tot, mt * 16 + hf * 8 + (lane >> 2));

    float best[2][2] = {{3.402823466e38f, 3.402823466e38f},
                        {3.402823466e38f, 3.402823466e38f}};
    int   bi[2][2]   = {{0, 0}, {0, 0}};

    uint32_t abase[2];
    #pragma unroll
    for (int mt = 0; mt < 2; mt++)
        abase[mt] = su + (uint32_t)(p0 + mt * 16 + (lane & 15)) * 256u;
    const uint32_t arsw0 = (uint32_t)((p0 + (lane & 15)) & 7);
    const int akg  = lane >> 4;
    const int brow_local = ((lane >> 4) << 3) + (lane & 7);
    const int bkg_half   = (lane >> 3) & 1;

    for (int ch = 0; ch < P3_CHN; ch++) {
        const int buf = ch % P3_NBUF;
        if (ch + 1 < P3_CHN) { CP_WAIT1(); } else { CP_WAIT0(); }
        __syncthreads();
        if (ch + 2 < P3_CHN) p3_issue_b(su, tid, ch + 2, (ch + 2) % P3_NBUF);

        float2 c2p[4];
        #pragma unroll
        for (int nt = 0; nt < 4; nt++)
            c2p[nt] = __ldg((const float2*)(g_c2 + ch * P3_CHW + nt * 8 + 2 * (lane & 3)));

        float D[2][4][4];
        #pragma unroll
        for (int mt = 0; mt < 2; mt++)
            #pragma unroll
            for (int i = 0; i < 4; i++)
                #pragma unroll
                for (int j = 0; j < 4; j++) D[mt][i][j] = 0.0f;

        const uint32_t bbase = su + P3_B + (uint32_t)buf * P3_BBUF;

        #pragma unroll
        for (int ks = 0; ks < 8; ks++) {
            uint32_t A_[2][2][4];
            {
                uint32_t ag = (uint32_t)(ks * 2 + akg);
                uint32_t asw = ((ag ^ arsw0) << 4);
                #pragma unroll
                for (int mt = 0; mt < 2; mt++) {
                    ldsm_x4(A_[0][mt], abase[mt] + 0 * P3_A_SPLIT + asw);
                    ldsm_x4(A_[1][mt], abase[mt] + 1 * P3_A_SPLIT + asw);
                }
            }
            uint32_t B_[2][2][4];
            #pragma unroll
            for (int pp = 0; pp < 2; pp++) {
                int r  = pp * 16 + brow_local;
                int kg = ks * 2 + bkg_half;
                uint32_t bad = bbase + (uint32_t)r * 256u + ((uint32_t)(kg ^ (r & 7)) << 4);
                ldsm_x4(B_[0][pp], bad + 0 * P3_BSPLIT);
                ldsm_x4(B_[1][pp], bad + 1 * P3_BSPLIT);
            }
            const int SA[3] = {0, 0, 1};
            const int SB[3] = {0, 1, 0};
            #pragma unroll
            for (int p3 = 0; p3 < 3; p3++)
                #pragma unroll
                for (int mt = 0; mt < 2; mt++)
                    #pragma unroll
                    for (int pp = 0; pp < 2; pp++) {
                        mma_f16(D[mt][pp * 2 + 0], A_[SA[p3]][mt], B_[SB[p3]][pp][0], B_[SB[p3]][pp][1]);
                        mma_f16(D[mt][pp * 2 + 1], A_[SA[p3]][mt], B_[SB[p3]][pp][2], B_[SB[p3]][pp][3]);
                    }
        }

        #pragma unroll
        for (int nt = 0; nt < 4; nt++) {
            int cb = ch * P3_CHW + nt * 8 + 2 * (lane & 3);
            float c20 = c2p[nt].x, c21 = c2p[nt].y;
            #pragma unroll
            for (int mt = 0; mt < 2; mt++) {
                float v;
                v = (c20 + x2r[mt][0]) + D[mt][nt][0]; if (v < best[mt][0]) { best[mt][0] = v; bi[mt][0] = cb; }
                v = (c21 + x2r[mt][0]) + D[mt][nt][1]; if (v < best[mt][0]) { best[mt][0] = v; bi[mt][0] = cb + 1; }
                v = (c20 + x2r[mt][1]) + D[mt][nt][2]; if (v < best[mt][1]) { best[mt][1] = v; bi[mt][1] = cb; }
                v = (c21 + x2r[mt][1]) + D[mt][nt][3]; if (v < best[mt][1]) { best[mt][1] = v; bi[mt][1] = cb + 1; }
            }
        }
    }

    #pragma unroll
    for (int off = 1; off < 4; off <<= 1) {
        #pragma unroll
        for (int mt = 0; mt < 2; mt++)
            #pragma unroll
            for (int hf = 0; hf < 2; hf++) {
                float ov = __shfl_xor_sync(0xffffffffu, best[mt][hf], off);
                int   oi = __shfl_xor_sync(0xffffffffu, bi[mt][hf],   off);
                if (ov < best[mt][hf] || (ov == best[mt][hf] && oi < bi[mt][hf])) {
                    best[mt][hf] = ov; bi[mt][hf] = oi;
                }
            }
    }
    if ((lane & 3) == 0) {
        #pragma unroll
        for (int mt = 0; mt < 2; mt++)
            #pragma unroll
            for (int hf = 0; hf < 2; hf++) {
                int rA = p0 + mt * 16 + hf * 8 + (lane >> 2);
                int fi = base + rA;
                if (fi < cnt) out_asg[g_flagged[fi]] = (float)bi[mt][hf];
            }
    }
}

// ---------------- launch ----------------
extern "C" void kernel_launch(void* const* d_in, const int* in_sizes, int n_in,
                              void* d_out, int out_size) {
    const float* vecs = (const float*)d_in[0];
    const int*   asg  = (const int*)d_in[1];
    float* out      = (float*)d_out;
    float* out_cent = out;             // [KC*DIM]
    float* out_asg  = out + KC * DIM;  // [NPTS]

    zero_kernel<<<(KC * DIM + 255) / 256, 256>>>();
    segsum_kernel<<<(NPTS * 32) / 256, 256>>>(vecs, asg);
    finalize_kernel<<<KC, DIM>>>(out_cent);

    int ablocks = (NPTS + PTS_CTA - 1) / PTS_CTA;
    cudaFuncSetAttribute(phase1_kernel,
                         cudaFuncAttributeMaxDynamicSharedMemorySize, P1_SM);
    phase1_kernel<<<ablocks, THR, P1_SM>>>(vecs, out_asg);

    cudaFuncSetAttribute(phase3_kernel,
                         cudaFuncAttributeMaxDynamicSharedMemorySize, P3_SM);
    phase3_kernel<<<ablocks, THR, P3_SM>>>(vecs, out_asg);
}

// round 16
// speedup vs baseline: 1.8140x; 1.0526x over previous
#include <cuda_runtime.h>
#include <cuda_fp16.h>
#include <cstdint>
#include <cstddef>

#define NPTS 500000
#define DIM  128
#define KC   1024

// ---------------- scratch ----------------
__device__ float g_sums[KC * DIM];
__device__ float g_counts[KC];
__device__ float g_c2[KC];
__device__ __half g_cent_hi[KC * DIM];   // fp16 splits of -2*centroid
__device__ __half g_cent_mi[KC * DIM];
__device__ int   g_flagged[NPTS];
__device__ int   g_nflag;
__device__ int   g_maxmh_bits;
__device__ int   g_maxmm_bits;

// ---------------- helpers ----------------
__device__ __forceinline__ uint32_t smem_u32(const void* p) {
    uint32_t a;
    asm("{ .reg .u64 t; cvta.to.shared.u64 t, %1; cvt.u32.u64 %0, t; }" : "=r"(a) : "l"(p));
    return a;
}
__device__ __forceinline__ void ldsm_x4(uint32_t* r, uint32_t addr) {
    asm volatile("ldmatrix.sync.aligned.m8n8.x4.shared.b16 {%0,%1,%2,%3}, [%4];"
        : "=r"(r[0]), "=r"(r[1]), "=r"(r[2]), "=r"(r[3]) : "r"(addr));
}
__device__ __forceinline__ void mma_f16(float* d, const uint32_t* a, uint32_t b0, uint32_t b1) {
    asm volatile("mma.sync.aligned.m16n8k16.row.col.f32.f16.f16.f32 "
        "{%0,%1,%2,%3}, {%4,%5,%6,%7}, {%8,%9}, {%0,%1,%2,%3};"
        : "+f"(d[0]), "+f"(d[1]), "+f"(d[2]), "+f"(d[3])
        : "r"(a[0]), "r"(a[1]), "r"(a[2]), "r"(a[3]), "r"(b0), "r"(b1));
}
__device__ __forceinline__ void cp16(uint32_t dst, const void* src) {
    asm volatile("cp.async.cg.shared.global [%0], [%1], 16;" :: "r"(dst), "l"(src) : "memory");
}
#define CP_COMMIT() asm volatile("cp.async.commit_group;" ::: "memory")
#define CP_WAIT0()  asm volatile("cp.async.wait_group 0;" ::: "memory")
#define CP_WAIT1()  asm volatile("cp.async.wait_group 1;" ::: "memory")

// ---------------- kernel 1: zero scratch ----------------
__global__ void zero_kernel() {
    int i = blockIdx.x * blockDim.x + threadIdx.x;
    if (i < KC * DIM) g_sums[i] = 0.0f;
    if (i < KC)       g_counts[i] = 0.0f;
    if (i == 0) { g_nflag = 0; g_maxmh_bits = 0; g_maxmm_bits = 0; }
}

// ---------------- kernel 2: segment sum ----------------
__global__ void segsum_kernel(const float* __restrict__ vecs,
                              const int*   __restrict__ asg) {
    int gw   = (blockIdx.x * blockDim.x + threadIdx.x) >> 5;
    int lane = threadIdx.x & 31;
    if (gw >= NPTS) return;
    int k = asg[gw];
    float4 v = *((const float4*)(vecs + (size_t)gw * DIM) + lane);
    atomicAdd(((float4*)(g_sums + (size_t)k * DIM)) + lane, v);
    if (lane == 0) atomicAdd(&g_counts[k], 1.0f);
}

// ---------------- kernel 3: centroids, c2, splits, split norms ----------------
__global__ void finalize_kernel(float* __restrict__ out_cent) {
    int k = blockIdx.x;
    int d = threadIdx.x;
    float c = g_sums[k * DIM + d] / g_counts[k];
    out_cent[k * DIM + d] = c;

    float m = -2.0f * c;
    __half h = __float2half_rn(m);
    float mhf = __half2float(h);
    float mmr = m - mhf;
    __half mi = __float2half_rn(mmr);
    g_cent_hi[k * DIM + d] = h;
    g_cent_mi[k * DIM + d] = mi;

    float s  = c * c;
    float sh = mhf * mhf;
    float sr = mmr * mmr;
    #pragma unroll
    for (int o = 16; o > 0; o >>= 1) {
        s  += __shfl_down_sync(0xffffffffu, s,  o);
        sh += __shfl_down_sync(0xffffffffu, sh, o);
        sr += __shfl_down_sync(0xffffffffu, sr, o);
    }
    __shared__ float ws[4], wh[4], wr[4];
    if ((d & 31) == 0) { ws[d >> 5] = s; wh[d >> 5] = sh; wr[d >> 5] = sr; }
    __syncthreads();
    if (d == 0) {
        g_c2[k] = (ws[0] + ws[1]) + (ws[2] + ws[3]);
        float nh = sqrtf((wh[0] + wh[1]) + (wh[2] + wh[3]));
        float nr = sqrtf((wr[0] + wr[1]) + (wr[2] + wr[3]));
        atomicMax(&g_maxmh_bits, __float_as_int(nh));
        atomicMax(&g_maxmm_bits, __float_as_int(nr));
    }
}

// ================= phase 1: hh-only MMA argmin + certification =================
// 128 points/CTA x 1024 clusters. CHW=64 chunks (16). NBUF=2 double buffer,
// race-free: sync -> issue(ch+1) into buffer (ch+1)%2 (just released) -> wait.
// Surrogate = c2 + D (x2 dropped). Immediate top-2-of-16 FMNMX fold with
// 4-bit packed candidate index. smem 64.5KB + regs<=170 -> 3 CTAs/SM.
#define PTS_CTA 128
#define THR     128
#define P1_CHN  16
#define P1_CHW  64
#define P1_A    0
#define P1_B    32768
#define P1_BBUF 16384
#define P1_SM   (P1_B + 2 * P1_BBUF)          // 65536 -> 3 CTAs/SM

__device__ __forceinline__ void p1_issue_b(uint32_t su, int tid, int ch, int buf) {
    const char* gb = (const char*)(g_cent_hi + (size_t)ch * P1_CHW * DIM);
    #pragma unroll
    for (int it = 0; it < 8; it++) {
        int idx = tid + it * THR;          // 0..1023
        int row = idx >> 4, kg = idx & 15;
        uint32_t dst = su + P1_B + (uint32_t)buf * P1_BBUF + (uint32_t)row * 256u
                     + ((uint32_t)(kg ^ (row & 7)) << 4);
        cp16(dst, gb + (size_t)idx * 16);
    }
    CP_COMMIT();
}

__global__ __launch_bounds__(THR, 3)
void phase1_kernel(const float* __restrict__ vecs, float* __restrict__ out_asg) {
    extern __shared__ __align__(1024) char sm[];
    const uint32_t su = smem_u32(sm);
    const int tid  = threadIdx.x;
    const int lane = tid & 31;
    const int w    = tid >> 5;
    const int base = blockIdx.x * PTS_CTA;

    const float maxMh = __int_as_float(g_maxmh_bits);
    const float maxMm = __int_as_float(g_maxmm_bits);

    p1_issue_b(su, tid, 0, 0);
    p1_issue_b(su, tid, 1, 1);

    // A convert: fp32 -> xh fp16 (smem); ||xh||^2, ||xmr||^2 for the bound
    float xh2 = 0.0f, xmr2 = 0.0f;
    {
        int p = tid;
        int n = base + p; if (n >= NPTS) n = NPTS - 1;
        const uint32_t rowb = (uint32_t)p * 256u;
        const uint32_t psw  = (uint32_t)(p & 7);
        const float4* src = (const float4*)(vecs + (size_t)n * DIM);
        #pragma unroll
        for (int j = 0; j < 32; j++) {
            float4 v = src[j];
            int d0 = j * 4;
            #pragma unroll
            for (int q = 0; q < 2; q++) {
                float a0 = q ? v.z : v.x;
                float a1 = q ? v.w : v.y;
                int   d  = d0 + 2 * q;
                __half h0 = __float2half_rn(a0);
                __half h1 = __float2half_rn(a1);
                float f0 = __half2float(h0), f1 = __half2float(h1);
                float r0 = a0 - f0, r1 = a1 - f1;
                xh2  = fmaf(f0, f0, xh2);  xh2  = fmaf(f1, f1, xh2);
                xmr2 = fmaf(r0, r0, xmr2); xmr2 = fmaf(r1, r1, xmr2);
                uint32_t off = rowb + ((((uint32_t)(d >> 3)) ^ psw) << 4) + (uint32_t)(d & 7) * 2u;
                __half2 ph(h0, h1);
                *(uint32_t*)(sm + P1_A + off) = *(uint32_t*)&ph;
            }
        }
    }

    const int p0 = w * 32;
    float thr[2][2];
    #pragma unroll
    for (int mt = 0; mt < 2; mt++)
        #pragma unroll
        for (int hf = 0; hf < 2; hf++) {
            int sl = mt * 16 + hf * 8 + (lane >> 2);
            float a2 = __shfl_sync(0xffffffffu, xmr2, sl);
            float h2 = __shfl_sync(0xffffffffu, xh2,  sl);
            thr[mt][hf] = 3.0f * (sqrtf(a2) * (maxMh + maxMm) + sqrtf(h2) * maxMm) + 1.5e-3f;
        }

    float b1[2][2] = {{3.402823466e38f, 3.402823466e38f},
                      {3.402823466e38f, 3.402823466e38f}};
    float b2[2][2] = {{3.402823466e38f, 3.402823466e38f},
                      {3.402823466e38f, 3.402823466e38f}};
    int   i1[2][2] = {{0, 0}, {0, 0}};

    uint32_t abase[2];
    #pragma unroll
    for (int mt = 0; mt < 2; mt++)
        abase[mt] = su + P1_A + (uint32_t)(p0 + mt * 16 + (lane & 15)) * 256u;
    const uint32_t arsw0 = (uint32_t)((p0 + (lane & 15)) & 7);
    const int akg  = lane >> 4;
    const int brow_local = ((lane >> 4) << 3) + (lane & 7);
    const int bkg_half   = (lane >> 3) & 1;
    const int lidx4      = 2 * (lane & 3);

    for (int ch = 0; ch < P1_CHN; ch++) {
        const int buf = ch & 1;
        // sync first: all warps done reading buffer (ch+1)&1 (used at ch-1)
        __syncthreads();
        if (ch >= 1 && ch + 1 < P1_CHN)
            p1_issue_b(su, tid, ch + 1, (ch + 1) & 1);
        if (ch + 1 < P1_CHN) { CP_WAIT1(); } else { CP_WAIT0(); }

        // prefetch c2 for this chunk's fold
        float2 c2p[8];
        #pragma unroll
        for (int nt = 0; nt < 8; nt++)
            c2p[nt] = __ldg((const float2*)(g_c2 + ch * P1_CHW + nt * 8 + lidx4));

        float D[2][8][4];
        #pragma unroll
        for (int mt = 0; mt < 2; mt++)
            #pragma unroll
            for (int i = 0; i < 8; i++)
                #pragma unroll
                for (int j = 0; j < 4; j++) D[mt][i][j] = 0.0f;

        const uint32_t bbase = su + P1_B + (uint32_t)buf * P1_BBUF;

        #pragma unroll
        for (int ks = 0; ks < 8; ks++) {
            uint32_t A_[2][4];
            {
                uint32_t ag = (uint32_t)(ks * 2 + akg);
                uint32_t asw = ((ag ^ arsw0) << 4);
                #pragma unroll
                for (int mt = 0; mt < 2; mt++)
                    ldsm_x4(A_[mt], abase[mt] + asw);
            }
            uint32_t B_[4][4];
            #pragma unroll
            for (int pp = 0; pp < 4; pp++) {
                int r  = pp * 16 + brow_local;
                int kg = ks * 2 + bkg_half;
                uint32_t bad = bbase + (uint32_t)r * 256u + ((uint32_t)(kg ^ (r & 7)) << 4);
                ldsm_x4(B_[pp], bad);
            }
            #pragma unroll
            for (int mt = 0; mt < 2; mt++)
                #pragma unroll
                for (int pp = 0; pp < 4; pp++) {
                    mma_f16(D[mt][pp * 2 + 0], A_[mt], B_[pp][0], B_[pp][1]);
                    mma_f16(D[mt][pp * 2 + 1], A_[mt], B_[pp][2], B_[pp][3]);
                }
        }

        // ---- immediate fold: top-2-of-16 FMNMX network, 4-bit packed idx ----
        #pragma unroll
        for (int mt = 0; mt < 2; mt++)
            #pragma unroll
            for (int hf = 0; hf < 2; hf++) {
                float mn[8], mx[8];
                #pragma unroll
                for (int nt = 0; nt < 8; nt++) {
                    float v0 = c2p[nt].x + D[mt][nt][hf * 2 + 0];
                    float v1 = c2p[nt].y + D[mt][nt][hf * 2 + 1];
                    float p0f = __uint_as_float((__float_as_uint(v0) & 0xFFFFFFF0u) | (uint32_t)(nt * 2 + 0));
                    float p1f = __uint_as_float((__float_as_uint(v1) & 0xFFFFFFF0u) | (uint32_t)(nt * 2 + 1));
                    mn[nt] = fminf(p0f, p1f);
                    mx[nt] = fmaxf(p0f, p1f);
                }
                float a0 = fminf(mn[0], mn[1]), A0 = fmaxf(mn[0], mn[1]);
                float a1 = fminf(mn[2], mn[3]), A1 = fmaxf(mn[2], mn[3]);
                float a2 = fminf(mn[4], mn[5]), A2 = fmaxf(mn[4], mn[5]);
                float a3 = fminf(mn[6], mn[7]), A3 = fmaxf(mn[6], mn[7]);
                float m0 = fminf(a0, a1), s0 = fminf(fmaxf(a0, a1), fminf(A0, A1));
                float m1 = fminf(a2, a3), s1 = fminf(fmaxf(a2, a3), fminf(A2, A3));
                float WIN = fminf(m0, m1);
                float S_m = fminf(fmaxf(m0, m1), fminf(s0, s1));
                float mM = fminf(fminf(fminf(mx[0], mx[1]), fminf(mx[2], mx[3])),
                                 fminf(fminf(mx[4], mx[5]), fminf(mx[6], mx[7])));
                float S = fminf(S_m, mM);
                b2[mt][hf] = fminf(fminf(b2[mt][hf], S), fmaxf(b1[mt][hf], WIN));
                if (WIN < b1[mt][hf]) {
                    uint32_t j = __float_as_uint(WIN) & 15u;
                    i1[mt][hf] = ch * P1_CHW + (int)(((j >> 1) << 3) | (j & 1)) + lidx4;
                    b1[mt][hf] = WIN;
                }
            }
    }

    // cross-lane 2-min merge over the 4 lanes sharing each point row
    #pragma unroll
    for (int off = 1; off < 4; off <<= 1) {
        #pragma unroll
        for (int mt = 0; mt < 2; mt++)
            #pragma unroll
            for (int hf = 0; hf < 2; hf++) {
                float o1 = __shfl_xor_sync(0xffffffffu, b1[mt][hf], off);
                int   oi = __shfl_xor_sync(0xffffffffu, i1[mt][hf], off);
                float o2 = __shfl_xor_sync(0xffffffffu, b2[mt][hf], off);
                float hi = fmaxf(b1[mt][hf], o1);
                b2[mt][hf] = fminf(fminf(b2[mt][hf], o2), hi);
                if (o1 < b1[mt][hf] || (o1 == b1[mt][hf] && oi < i1[mt][hf])) {
                    b1[mt][hf] = o1; i1[mt][hf] = oi;
                }
            }
    }

    if ((lane & 3) == 0) {
        #pragma unroll
        for (int mt = 0; mt < 2; mt++)
            #pragma unroll
            for (int hf = 0; hf < 2; hf++) {
                int rA = p0 + mt * 16 + hf * 8 + (lane >> 2);
                int n  = base + rA;
                if (n < NPTS) {
                    out_asg[n] = (float)i1[mt][hf];
                    if (!(b2[mt][hf] - b1[mt][hf] > thr[mt][hf])) {
                        int s = atomicAdd(&g_nflag, 1);
                        g_flagged[s] = n;
                    }
                }
            }
    }
}

// ================= phase 3: 3-pass refine on flagged points =================
// Identical math to the validated round-9/10 kernel; points via g_flagged.
#define P3_CHN     32
#define P3_CHW     32
#define P3_A_SPLIT 32768
#define P3_B       65536
#define P3_BBUF    16384
#define P3_BSPLIT  8192
#define P3_NBUF    3
#define P3_SM      (P3_B + P3_NBUF * P3_BBUF)   // 114688 -> 2 CTAs/SM

__device__ __forceinline__ void p3_issue_b(uint32_t su, int tid, int ch, int buf) {
    #pragma unroll
    for (int s = 0; s < 2; s++) {
        const __half* g = (s == 0) ? g_cent_hi : g_cent_mi;
        const char* gb = (const char*)(g + (size_t)ch * P3_CHW * DIM);
        #pragma unroll
        for (int it = 0; it < 4; it++) {
            int idx = tid + it * THR;
            int row = idx >> 4, kg = idx & 15;
            uint32_t dst = su + P3_B + (uint32_t)buf * P3_BBUF
                         + (uint32_t)s * P3_BSPLIT + (uint32_t)row * 256u
                         + ((uint32_t)(kg ^ (row & 7)) << 4);
            cp16(dst, gb + (size_t)idx * 16);
        }
    }
    CP_COMMIT();
}

__global__ __launch_bounds__(THR, 2)
void phase3_kernel(const float* __restrict__ vecs, float* __restrict__ out_asg) {
    const int cnt = g_nflag;
    const int base = blockIdx.x * PTS_CTA;
    if (base >= cnt) return;

    extern __shared__ __align__(1024) char sm[];
    const uint32_t su = smem_u32(sm);
    const int tid  = threadIdx.x;
    const int lane = tid & 31;
    const int w    = tid >> 5;

    p3_issue_b(su, tid, 0, 0);
    p3_issue_b(su, tid, 1, 1);

    float s2tot;
    {
        int p = tid;
        int fi = base + p;
        int n = (fi < cnt) ? g_flagged[fi] : g_flagged[0];
        const uint32_t rowb = (uint32_t)p * 256u;
        const uint32_t psw  = (uint32_t)(p & 7);
        float s2h[2];
        #pragma unroll
        for (int h = 0; h < 2; h++) {
            const float4* src = (const float4*)(vecs + (size_t)n * DIM) + h * 16;
            float s2 = 0.0f;
            #pragma unroll
            for (int j = 0; j < 16; j++) {
                float4 v = src[j];
                int d0 = h * 64 + j * 4;
                #pragma unroll
                for (int q = 0; q < 2; q++) {
                    float a0 = q ? v.z : v.x;
                    float a1 = q ? v.w : v.y;
                    int   d  = d0 + 2 * q;
                    s2 = fmaf(a0, a0, s2); s2 = fmaf(a1, a1, s2);
                    __half h0 = __float2half_rn(a0);
                    __half m0 = __float2half_rn(a0 - __half2float(h0));
                    __half h1 = __float2half_rn(a1);
                    __half m1 = __float2half_rn(a1 - __half2float(h1));
                    uint32_t off = rowb + ((((uint32_t)(d >> 3)) ^ psw) << 4) + (uint32_t)(d & 7) * 2u;
                    __half2 ph(h0, h1), pm(m0, m1);
                    *(uint32_t*)(sm + 0 * P3_A_SPLIT + off) = *(uint32_t*)&ph;
                    *(uint32_t*)(sm + 1 * P3_A_SPLIT + off) = *(uint32_t*)&pm;
                }
            }
            s2h[h] = s2;
        }
        s2tot = s2h[0] + s2h[1];
    }
    __syncthreads();

    const int p0 = w * 32;
    float x2r[2][2];
    #pragma unroll
    for (int mt = 0; mt < 2; mt++)
        #pragma unroll
        for (int hf = 0; hf < 2; hf++)
            x2r[mt][hf] = __shfl_sync(0xffffffffu, s2tot, mt * 16 + hf * 8 + (lane >> 2));

    float best[2][2] = {{3.402823466e38f, 3.402823466e38f},
                        {3.402823466e38f, 3.402823466e38f}};
    int   bi[2][2]   = {{0, 0}, {0, 0}};

    uint32_t abase[2];
    #pragma unroll
    for (int mt = 0; mt < 2; mt++)
        abase[mt] = su + (uint32_t)(p0 + mt * 16 + (lane & 15)) * 256u;
    const uint32_t arsw0 = (uint32_t)((p0 + (lane & 15)) & 7);
    const int akg  = lane >> 4;
    const int brow_local = ((lane >> 4) << 3) + (lane & 7);
    const int bkg_half   = (lane >> 3) & 1;

    for (int ch = 0; ch < P3_CHN; ch++) {
        const int buf = ch % P3_NBUF;
        if (ch + 1 < P3_CHN) { CP_WAIT1(); } else { CP_WAIT0(); }
        __syncthreads();
        if (ch + 2 < P3_CHN) p3_issue_b(su, tid, ch + 2, (ch + 2) % P3_NBUF);

        float2 c2p[4];
        #pragma unroll
        for (int nt = 0; nt < 4; nt++)
            c2p[nt] = __ldg((const float2*)(g_c2 + ch * P3_CHW + nt * 8 + 2 * (lane & 3)));

        float D[2][4][4];
        #pragma unroll
        for (int mt = 0; mt < 2; mt++)
            #pragma unroll
            for (int i = 0; i < 4; i++)
                #pragma unroll
                for (int j = 0; j < 4; j++) D[mt][i][j] = 0.0f;

        const uint32_t bbase = su + P3_B + (uint32_t)buf * P3_BBUF;

        #pragma unroll
        for (int ks = 0; ks < 8; ks++) {
            uint32_t A_[2][2][4];
            {
                uint32_t ag = (uint32_t)(ks * 2 + akg);
                uint32_t asw = ((ag ^ arsw0) << 4);
                #pragma unroll
                for (int mt = 0; mt < 2; mt++) {
                    ldsm_x4(A_[0][mt], abase[mt] + 0 * P3_A_SPLIT + asw);
                    ldsm_x4(A_[1][mt], abase[mt] + 1 * P3_A_SPLIT + asw);
                }
            }
            uint32_t B_[2][2][4];
            #pragma unroll
            for (int pp = 0; pp < 2; pp++) {
                int r  = pp * 16 + brow_local;
                int kg = ks * 2 + bkg_half;
                uint32_t bad = bbase + (uint32_t)r * 256u + ((uint32_t)(kg ^ (r & 7)) << 4);
                ldsm_x4(B_[0][pp], bad + 0 * P3_BSPLIT);
                ldsm_x4(B_[1][pp], bad + 1 * P3_BSPLIT);
            }
            const int SA[3] = {0, 0, 1};
            const int SB[3] = {0, 1, 0};
            #pragma unroll
            for (int p3 = 0; p3 < 3; p3++)
                #pragma unroll
                for (int mt = 0; mt < 2; mt++)
                    #pragma unroll
                    for (int pp = 0; pp < 2; pp++) {
                        mma_f16(D[mt][pp * 2 + 0], A_[SA[p3]][mt], B_[SB[p3]][pp][0], B_[SB[p3]][pp][1]);
                        mma_f16(D[mt][pp * 2 + 1], A_[SA[p3]][mt], B_[SB[p3]][pp][2], B_[SB[p3]][pp][3]);
                    }
        }

        #pragma unroll
        for (int nt = 0; nt < 4; nt++) {
            int cb = ch * P3_CHW + nt * 8 + 2 * (lane & 3);
            float c20 = c2p[nt].x, c21 = c2p[nt].y;
            #pragma unroll
            for (int mt = 0; mt < 2; mt++) {
                float v;
                v = (c20 + x2r[mt][0]) + D[mt][nt][0]; if (v < best[mt][0]) { best[mt][0] = v; bi[mt][0] = cb; }
                v = (c21 + x2r[mt][0]) + D[mt][nt][1]; if (v < best[mt][0]) { best[mt][0] = v; bi[mt][0] = cb + 1; }
                v = (c20 + x2r[mt][1]) + D[mt][nt][2]; if (v < best[mt][1]) { best[mt][1] = v; bi[mt][1] = cb; }
                v = (c21 + x2r[mt][1]) + D[mt][nt][3]; if (v < best[mt][1]) { best[mt][1] = v; bi[mt][1] = cb + 1; }
            }
        }
    }

    #pragma unroll
    for (int off = 1; off < 4; off <<= 1) {
        #pragma unroll
        for (int mt = 0; mt < 2; mt++)
            #pragma unroll
            for (int hf = 0; hf < 2; hf++) {
                float ov = __shfl_xor_sync(0xffffffffu, best[mt][hf], off);
                int   oi = __shfl_xor_sync(0xffffffffu, bi[mt][hf],   off);
                if (ov < best[mt][hf] || (ov == best[mt][hf] && oi < bi[mt][hf])) {
                    best[mt][hf] = ov; bi[mt][hf] = oi;
                }
            }
    }
    if ((lane & 3) == 0) {
        #pragma unroll
        for (int mt = 0; mt < 2; mt++)
            #pragma unroll
            for (int hf = 0; hf < 2; hf++) {
                int rA = p0 + mt * 16 + hf * 8 + (lane >> 2);
                int fi = base + rA;
                if (fi < cnt) out_asg[g_flagged[fi]] = (float)bi[mt][hf];
            }
    }
}

// ---------------- launch ----------------
extern "C" void kernel_launch(void* const* d_in, const int* in_sizes, int n_in,
                              void* d_out, int out_size) {
    const float* vecs = (const float*)d_in[0];
    const int*   asg  = (const int*)d_in[1];
    float* out      = (float*)d_out;
    float* out_cent = out;             // [KC*DIM]
    float* out_asg  = out + KC * DIM;  // [NPTS]

    zero_kernel<<<(KC * DIM + 255) / 256, 256>>>();
    segsum_kernel<<<(NPTS * 32) / 256, 256>>>(vecs, asg);
    finalize_kernel<<<KC, DIM>>>(out_cent);

    int ablocks = (NPTS + PTS_CTA - 1) / PTS_CTA;
    cudaFuncSetAttribute(phase1_kernel,
                         cudaFuncAttributeMaxDynamicSharedMemorySize, P1_SM);
    phase1_kernel<<<ablocks, THR, P1_SM>>>(vecs, out_asg);

    cudaFuncSetAttribute(phase3_kernel,
                         cudaFuncAttributeMaxDynamicSharedMemorySize, P3_SM);
    phase3_kernel<<<ablocks, THR, P3_SM>>>(vecs, out_asg);
}